// round 1
// baseline (speedup 1.0000x reference)
#include <cuda_runtime.h>
#include <cstdint>
#include <cstddef>

#define N_NODES 40960
#define N_EDGES 131072
#define BATCH   1024
#define NPG     40      // nodes per graph

// ---------------- scratch (no allocs allowed) ----------------
__device__ float g_H [N_NODES * 312];
__device__ float g_A [N_NODES * 312];
__device__ float g_B2[N_NODES * 312];
__device__ float g_dinv[N_NODES];
__device__ float g_pool[BATCH * 312];
__device__ float g_p1 [BATCH * 156];
__device__ float g_cv1[BATCH * 512];
__device__ float g_cv2[BATCH * 256];
__device__ float g_xc [BATCH * 384];
__device__ float g_f1 [BATCH * 512];
__device__ float g_f2 [BATCH * 128];
__device__ float g_rn [BATCH];

// ---------------- tf32 GEMM ----------------
#define BM 64
#define BN 64
#define BK 32

__device__ __forceinline__ unsigned f2tf32(float f) {
    unsigned u;
    asm("cvt.rna.tf32.f32 %0, %1;" : "=r"(u) : "f"(f));
    return u;
}

// C[M,N] = A[M,K] @ B[K,N]; A lda, B ldb, C ldc (row-major).
// epilogue: v = acc * (rowscale?rowscale[r]:1) + (bias?bias[c]:0); relu optional.
__global__ void __launch_bounds__(256) gemm_tf32(
    const float* __restrict__ A, int lda,
    const float* __restrict__ B, int ldb,
    float* __restrict__ C, int ldc,
    int M, int N, int K,
    const float* __restrict__ bias,
    const float* __restrict__ rowscale,
    int relu)
{
    __shared__ unsigned As[BM][BK + 1];
    __shared__ unsigned Bs[BK][BN + 1];

    const int tid  = threadIdx.x;
    const int lane = tid & 31;
    const int wid  = tid >> 5;
    const int wm   = wid & 1;      // 2 warp rows x 32
    const int wn   = wid >> 1;     // 4 warp cols x 16
    const int rowBase = blockIdx.y * BM;
    const int colBase = blockIdx.x * BN;

    float acc[2][2][4];
#pragma unroll
    for (int a = 0; a < 2; a++)
#pragma unroll
        for (int b = 0; b < 2; b++)
#pragma unroll
            for (int i = 0; i < 4; i++) acc[a][b][i] = 0.f;

    for (int k0 = 0; k0 < K; k0 += BK) {
        // load A tile (coalesced: 32 consecutive cols per warp)
#pragma unroll
        for (int idx = tid; idx < BM * BK; idx += 256) {
            int r = idx >> 5, c = idx & 31;
            int gr = rowBase + r, gc = k0 + c;
            float v = (gr < M && gc < K) ? A[(size_t)gr * lda + gc] : 0.f;
            As[r][c] = f2tf32(v);
        }
        // load B tile
#pragma unroll
        for (int idx = tid; idx < BK * BN; idx += 256) {
            int r = idx >> 6, c = idx & 63;
            int gr = k0 + r, gc = colBase + c;
            float v = (gr < K && gc < N) ? B[(size_t)gr * ldb + gc] : 0.f;
            Bs[r][c] = f2tf32(v);
        }
        __syncthreads();

#pragma unroll
        for (int ks = 0; ks < BK; ks += 8) {
            unsigned a[2][4], b[2][2];
            int ar = wm * 32 + (lane >> 2);
            int ak = ks + (lane & 3);
#pragma unroll
            for (int mt = 0; mt < 2; mt++) {
                a[mt][0] = As[ar + mt * 16     ][ak];
                a[mt][1] = As[ar + mt * 16 + 8 ][ak];
                a[mt][2] = As[ar + mt * 16     ][ak + 4];
                a[mt][3] = As[ar + mt * 16 + 8 ][ak + 4];
            }
            int bc = wn * 16 + (lane >> 2);
            int bk = ks + (lane & 3);
#pragma unroll
            for (int nt = 0; nt < 2; nt++) {
                b[nt][0] = Bs[bk    ][bc + nt * 8];
                b[nt][1] = Bs[bk + 4][bc + nt * 8];
            }
#pragma unroll
            for (int mt = 0; mt < 2; mt++)
#pragma unroll
                for (int nt = 0; nt < 2; nt++)
                    asm volatile(
                        "mma.sync.aligned.m16n8k8.row.col.f32.tf32.tf32.f32 "
                        "{%0,%1,%2,%3},{%4,%5,%6,%7},{%8,%9},{%0,%1,%2,%3};"
                        : "+f"(acc[mt][nt][0]), "+f"(acc[mt][nt][1]),
                          "+f"(acc[mt][nt][2]), "+f"(acc[mt][nt][3])
                        : "r"(a[mt][0]), "r"(a[mt][1]), "r"(a[mt][2]), "r"(a[mt][3]),
                          "r"(b[nt][0]), "r"(b[nt][1]));
        }
        __syncthreads();
    }

#pragma unroll
    for (int mt = 0; mt < 2; mt++)
#pragma unroll
        for (int nt = 0; nt < 2; nt++)
#pragma unroll
            for (int i = 0; i < 4; i++) {
                int r = rowBase + wm * 32 + mt * 16 + (lane >> 2) + ((i >= 2) ? 8 : 0);
                int c = colBase + wn * 16 + nt * 8 + 2 * (lane & 3) + (i & 1);
                if (r < M && c < N) {
                    float v = acc[mt][nt][i];
                    if (rowscale) v *= rowscale[r];
                    if (bias)     v += bias[c];
                    if (relu)     v = fmaxf(v, 0.f);
                    C[(size_t)r * ldc + c] = v;
                }
            }
}

// ---------------- GCN helper kernels ----------------
__global__ void k_deg_init(float* deg) {
    int i = blockIdx.x * blockDim.x + threadIdx.x;
    if (i < N_NODES) deg[i] = 1.f;
}
__global__ void k_deg_count(float* deg, const int* __restrict__ dst) {
    int e = blockIdx.x * blockDim.x + threadIdx.x;
    if (e < N_EDGES) atomicAdd(&deg[dst[e]], 1.f);
}
__global__ void k_rsqrt(float* d) {
    int i = blockIdx.x * blockDim.x + threadIdx.x;
    if (i < N_NODES) d[i] = rsqrtf(d[i]);
}

template <int VEC>
__global__ void k_scatter(float* __restrict__ OUT, const float* __restrict__ H,
                          int ld, const int* __restrict__ src, const int* __restrict__ dst,
                          const float* __restrict__ dinv, int fvec)
{
    int i = blockIdx.x * blockDim.x + threadIdx.x;
    int total = N_EDGES * fvec;
    if (i >= total) return;
    int e = i / fvec;
    int f = (i - e * fvec) * VEC;
    int s = src[e], d = dst[e];
    float nrm = dinv[s] * dinv[d];
    const float* hp = H + (size_t)s * ld + f;
    float* op = OUT + (size_t)d * ld + f;
    if (VEC == 4) {
        float4 h = *reinterpret_cast<const float4*>(hp);
        atomicAdd(op + 0, h.x * nrm);
        atomicAdd(op + 1, h.y * nrm);
        atomicAdd(op + 2, h.z * nrm);
        atomicAdd(op + 3, h.w * nrm);
    } else if (VEC == 2) {
        float2 h = *reinterpret_cast<const float2*>(hp);
        atomicAdd(op + 0, h.x * nrm);
        atomicAdd(op + 1, h.y * nrm);
    } else {
        atomicAdd(op, hp[0] * nrm);
    }
}

__global__ void k_finalize(float* __restrict__ OUT, const float* __restrict__ H,
                           int ld, const float* __restrict__ dinv,
                           const float* __restrict__ bias, int fo)
{
    int i = blockIdx.x * blockDim.x + threadIdx.x;
    int total = N_NODES * fo;
    if (i >= total) return;
    int node = i / fo;
    int f = i - node * fo;
    float di = dinv[node];
    size_t o = (size_t)node * ld + f;
    float v = OUT[o] + H[o] * (di * di) + bias[f];
    OUT[o] = fmaxf(v, 0.f);
}

__global__ void k_pool(float* __restrict__ pool, const float* __restrict__ X) {
    int i = blockIdx.x * blockDim.x + threadIdx.x;   // BATCH*312
    if (i >= BATCH * 312) return;
    int g = i / 312, f = i - g * 312;
    const float* p = X + (size_t)g * NPG * 312 + f;
    float m = p[0];
#pragma unroll 8
    for (int j = 1; j < NPG; j++) m = fmaxf(m, p[(size_t)j * 312]);
    pool[i] = m;
}

__global__ void k_rnorm(const float* __restrict__ cell, float* __restrict__ rn) {
    __shared__ float sm[256];
    int b = blockIdx.x;
    const float* row = cell + (size_t)b * 37261;
    float s = 0.f;
    for (int i = threadIdx.x; i < 37261; i += 256) { float v = row[i]; s += v * v; }
    sm[threadIdx.x] = s;
    __syncthreads();
    for (int off = 128; off > 0; off >>= 1) {
        if (threadIdx.x < off) sm[threadIdx.x] += sm[threadIdx.x + off];
        __syncthreads();
    }
    if (threadIdx.x == 0) rn[b] = 1.f / fmaxf(sqrtf(sm[0]), 1e-12f);
}

__global__ void k_out(const float* __restrict__ f2, const float* __restrict__ Wo,
                      const float* __restrict__ bo, float* __restrict__ out) {
    int i = blockIdx.x * blockDim.x + threadIdx.x;   // 2048
    if (i >= BATCH * 2) return;
    int b = i >> 1, o = i & 1;
    float s = bo[o];
    const float* fp = f2 + (size_t)b * 128;
#pragma unroll 8
    for (int k = 0; k < 128; k++) s += fp[k] * Wo[k * 2 + o];
    out[i] = s;
}

// ---------------- host orchestration ----------------
static inline dim3 ggrid(int M, int N) { return dim3((N + BN - 1) / BN, (M + BM - 1) / BM); }
static inline int  cdiv(int a, int b)  { return (a + b - 1) / b; }

static void run_branch(const float* x, const int* ei,
                       const float* Wc1, const float* bc1,
                       const float* Wc2, const float* bc2,
                       const float* Wc3, const float* bc3,
                       const float* Wg1, const float* bg1,
                       const float* Wg2, const float* bg2,
                       float* H_, float* A_, float* B_, float* dinv_,
                       float* pool_, float* p1_, float* xcDst)
{
    const int* src = ei;
    const int* dst = ei + N_EDGES;

    k_deg_init <<<cdiv(N_NODES, 256), 256>>>(dinv_);
    k_deg_count<<<cdiv(N_EDGES, 256), 256>>>(dinv_, dst);
    k_rsqrt    <<<cdiv(N_NODES, 256), 256>>>(dinv_);

    // conv1: 78 -> 78 (ld 80)
    gemm_tf32<<<ggrid(N_NODES, 78), 256>>>(x, 78, Wc1, 78, H_, 80,
                                           N_NODES, 78, 78, nullptr, nullptr, 0);
    cudaMemsetAsync(A_, 0, (size_t)N_NODES * 80 * sizeof(float));
    k_scatter<2><<<cdiv(N_EDGES * 39, 256), 256>>>(A_, H_, 80, src, dst, dinv_, 39);
    k_finalize  <<<cdiv(N_NODES * 78, 256), 256>>>(A_, H_, 80, dinv_, bc1, 78);

    // conv2: 78 -> 156
    gemm_tf32<<<ggrid(N_NODES, 156), 256>>>(A_, 80, Wc2, 156, H_, 156,
                                            N_NODES, 156, 78, nullptr, nullptr, 0);
    cudaMemsetAsync(B_, 0, (size_t)N_NODES * 156 * sizeof(float));
    k_scatter<4><<<cdiv(N_EDGES * 39, 256), 256>>>(B_, H_, 156, src, dst, dinv_, 39);
    k_finalize  <<<cdiv(N_NODES * 156, 256), 256>>>(B_, H_, 156, dinv_, bc2, 156);

    // conv3: 156 -> 312
    gemm_tf32<<<ggrid(N_NODES, 312), 256>>>(B_, 156, Wc3, 312, H_, 312,
                                            N_NODES, 312, 156, nullptr, nullptr, 0);
    cudaMemsetAsync(A_, 0, (size_t)N_NODES * 312 * sizeof(float));
    k_scatter<4><<<cdiv(N_EDGES * 78, 256), 256>>>(A_, H_, 312, src, dst, dinv_, 78);
    k_finalize  <<<cdiv(N_NODES * 312, 256), 256>>>(A_, H_, 312, dinv_, bc3, 312);

    // pool + MLP head
    k_pool<<<cdiv(BATCH * 312, 256), 256>>>(pool_, A_);
    gemm_tf32<<<ggrid(BATCH, 156), 256>>>(pool_, 312, Wg1, 156, p1_, 156,
                                          BATCH, 156, 312, bg1, nullptr, 1);
    gemm_tf32<<<ggrid(BATCH, 128), 256>>>(p1_, 156, Wg2, 128, xcDst, 384,
                                          BATCH, 128, 156, bg2, nullptr, 0);
}

extern "C" void kernel_launch(void* const* d_in, const int* in_sizes, int n_in,
                              void* d_out, int out_size)
{
    const float* x1   = (const float*)d_in[0];
    const int*   ei1  = (const int*)  d_in[1];
    const float* x2   = (const float*)d_in[3];
    const int*   ei2  = (const int*)  d_in[4];
    const float* cell = (const float*)d_in[6];
    const float *Wc1 = (const float*)d_in[7],  *bc1 = (const float*)d_in[8];
    const float *Wc2 = (const float*)d_in[9],  *bc2 = (const float*)d_in[10];
    const float *Wc3 = (const float*)d_in[11], *bc3 = (const float*)d_in[12];
    const float *Wg1 = (const float*)d_in[13], *bg1 = (const float*)d_in[14];
    const float *Wg2 = (const float*)d_in[15], *bg2 = (const float*)d_in[16];
    const float *Wr1 = (const float*)d_in[17], *br1 = (const float*)d_in[18];
    const float *Wr2 = (const float*)d_in[19], *br2 = (const float*)d_in[20];
    const float *Wr3 = (const float*)d_in[21], *br3 = (const float*)d_in[22];
    const float *Wf1 = (const float*)d_in[23], *bf1 = (const float*)d_in[24];
    const float *Wf2 = (const float*)d_in[25], *bf2 = (const float*)d_in[26];
    const float *Wo  = (const float*)d_in[27], *bo  = (const float*)d_in[28];

    float *H_, *A_, *B_, *dinv_, *pool_, *p1_, *cv1_, *cv2_, *xc_, *f1_, *f2_, *rn_;
    cudaGetSymbolAddress((void**)&H_,   g_H);
    cudaGetSymbolAddress((void**)&A_,   g_A);
    cudaGetSymbolAddress((void**)&B_,   g_B2);
    cudaGetSymbolAddress((void**)&dinv_,g_dinv);
    cudaGetSymbolAddress((void**)&pool_,g_pool);
    cudaGetSymbolAddress((void**)&p1_,  g_p1);
    cudaGetSymbolAddress((void**)&cv1_, g_cv1);
    cudaGetSymbolAddress((void**)&cv2_, g_cv2);
    cudaGetSymbolAddress((void**)&xc_,  g_xc);
    cudaGetSymbolAddress((void**)&f1_,  g_f1);
    cudaGetSymbolAddress((void**)&f2_,  g_f2);
    cudaGetSymbolAddress((void**)&rn_,  g_rn);

    // ---- cell branch (fuse row-normalization into GEMM epilogue) ----
    k_rnorm<<<BATCH, 256>>>(cell, rn_);
    gemm_tf32<<<ggrid(BATCH, 512), 256>>>(cell, 37261, Wr1, 512, cv1_, 512,
                                          BATCH, 512, 37261, br1, rn_, 1);
    gemm_tf32<<<ggrid(BATCH, 256), 256>>>(cv1_, 512, Wr2, 256, cv2_, 256,
                                          BATCH, 256, 512, br2, nullptr, 1);
    gemm_tf32<<<ggrid(BATCH, 128), 256>>>(cv2_, 256, Wr3, 128, xc_ + 256, 384,
                                          BATCH, 128, 256, br3, nullptr, 0);

    // ---- drug branches (shared weights, per reference) ----
    run_branch(x1, ei1, Wc1, bc1, Wc2, bc2, Wc3, bc3, Wg1, bg1, Wg2, bg2,
               H_, A_, B_, dinv_, pool_, p1_, xc_ + 0);
    run_branch(x2, ei2, Wc1, bc1, Wc2, bc2, Wc3, bc3, Wg1, bg1, Wg2, bg2,
               H_, A_, B_, dinv_, pool_, p1_, xc_ + 128);

    // ---- fusion head ----
    gemm_tf32<<<ggrid(BATCH, 512), 256>>>(xc_, 384, Wf1, 512, f1_, 512,
                                          BATCH, 512, 384, bf1, nullptr, 1);
    gemm_tf32<<<ggrid(BATCH, 128), 256>>>(f1_, 512, Wf2, 128, f2_, 128,
                                          BATCH, 128, 512, bf2, nullptr, 1);
    k_out<<<cdiv(BATCH * 2, 256), 256>>>(f2_, Wo, bo, (float*)d_out);
}

// round 2
// speedup vs baseline: 3.3050x; 3.3050x over previous
#include <cuda_runtime.h>
#include <cstdint>
#include <cstddef>

#define N_NODES 40960
#define N_EDGES 131072
#define BATCH   1024
#define NPG     40      // nodes per graph
#define BK      32
#define SPLITK  4

// ---------------- scratch (no allocs allowed) ----------------
__device__ float g_H [N_NODES * 312];
__device__ float g_A [N_NODES * 312];
__device__ float g_B2[N_NODES * 312];
__device__ float g_dinv[N_NODES];
__device__ float g_pool[BATCH * 312];
__device__ float g_p1 [BATCH * 156];
__device__ float g_acc[BATCH * 512];
__device__ float g_cv1[BATCH * 512];
__device__ float g_cv2[BATCH * 256];
__device__ float g_xc [BATCH * 384];
__device__ float g_f1 [BATCH * 512];
__device__ float g_f2 [BATCH * 128];
__device__ float g_rn [BATCH];

// ---------------- tf32 helpers ----------------
__device__ __forceinline__ unsigned f2tf32(float f) {
    unsigned u;
    asm("cvt.rna.tf32.f32 %0, %1;" : "=r"(u) : "f"(f));
    return u;
}
__device__ __forceinline__ void tf32split(float v, unsigned& h, unsigned& l) {
    h = f2tf32(v);
    float r = v - __uint_as_float(h);
    l = f2tf32(r);
}

#define MMA4(d, a0, a1, a2, a3, b0, b1)                                          \
    asm volatile(                                                                \
        "mma.sync.aligned.m16n8k8.row.col.f32.tf32.tf32.f32 "                    \
        "{%0,%1,%2,%3},{%4,%5,%6,%7},{%8,%9},{%0,%1,%2,%3};"                     \
        : "+f"((d)[0]), "+f"((d)[1]), "+f"((d)[2]), "+f"((d)[3])                 \
        : "r"(a0), "r"(a1), "r"(a2), "r"(a3), "r"(b0), "r"(b1))

// ---------------- pipelined 3xTF32 GEMM ----------------
// Tile 128(M) x 64(N) x 32(K), 256 threads = 8 warps (4 x 2), warp tile 32x32.
// Register-prefetched global loads (next tile's LDGs in flight during compute).
// PRECISE: 3xTF32 split (fp32-equivalent accuracy).
// ATOMIC: raw atomicAdd into accumulation buffer (split-K), no epilogue.
template<bool PRECISE, bool ATOMIC>
__global__ void __launch_bounds__(256) gemm_tc(
    const float* __restrict__ A, int lda,
    const float* __restrict__ B, int ldb,
    float* __restrict__ C, int ldc,
    int M, int N, int K, int kChunk,
    const float* __restrict__ bias,
    const float* __restrict__ rowscale,
    int relu)
{
    __shared__ float As[128][BK + 1];
    __shared__ float Bs[BK][64 + 1];

    const int tid  = threadIdx.x;
    const int lane = tid & 31;
    const int wid  = tid >> 5;
    const int wm   = wid & 3;        // 4 warp rows x 32
    const int wn   = wid >> 2;       // 2 warp cols x 32
    const int rowBase = blockIdx.y * 128;
    const int colBase = blockIdx.x * 64;
    const int kStart  = blockIdx.z * kChunk;
    const int kEnd    = min(K, kStart + kChunk);

    float acc[2][4][4];
#pragma unroll
    for (int a = 0; a < 2; a++)
#pragma unroll
        for (int b = 0; b < 4; b++)
#pragma unroll
            for (int i = 0; i < 4; i++) acc[a][b][i] = 0.f;

    float ra[16], rb[8];

    auto loadA = [&](int k0) {
#pragma unroll
        for (int i = 0; i < 16; i++) {
            int idx = tid + i * 256;
            int r = idx >> 5, c = idx & 31;
            int gr = rowBase + r, gc = k0 + c;
            ra[i] = (gr < M && gc < kEnd) ? A[(size_t)gr * lda + gc] : 0.f;
        }
    };
    auto loadB = [&](int k0) {
#pragma unroll
        for (int i = 0; i < 8; i++) {
            int idx = tid + i * 256;
            int r = idx >> 6, c = idx & 63;
            int gr = k0 + r, gc = colBase + c;
            rb[i] = (gr < kEnd && gc < N) ? B[(size_t)gr * ldb + gc] : 0.f;
        }
    };

    loadA(kStart);
    loadB(kStart);

    for (int k0 = kStart; k0 < kEnd; k0 += BK) {
        // stage current tile to smem
#pragma unroll
        for (int i = 0; i < 16; i++) { int idx = tid + i * 256; As[idx >> 5][idx & 31] = ra[i]; }
#pragma unroll
        for (int i = 0; i < 8;  i++) { int idx = tid + i * 256; Bs[idx >> 6][idx & 63] = rb[i]; }
        __syncthreads();

        // issue next tile's global loads now; they complete during compute
        if (k0 + BK < kEnd) { loadA(k0 + BK); loadB(k0 + BK); }

#pragma unroll
        for (int ks = 0; ks < BK; ks += 8) {
            unsigned ah[2][4], al[2][4], bh[4][2], bl[4][2];
            const int ar = wm * 32 + (lane >> 2);
            const int ak = ks + (lane & 3);
#pragma unroll
            for (int mt = 0; mt < 2; mt++) {
                float v0 = As[ar + mt * 16     ][ak];
                float v1 = As[ar + mt * 16 + 8 ][ak];
                float v2 = As[ar + mt * 16     ][ak + 4];
                float v3 = As[ar + mt * 16 + 8 ][ak + 4];
                if (PRECISE) {
                    tf32split(v0, ah[mt][0], al[mt][0]);
                    tf32split(v1, ah[mt][1], al[mt][1]);
                    tf32split(v2, ah[mt][2], al[mt][2]);
                    tf32split(v3, ah[mt][3], al[mt][3]);
                } else {
                    ah[mt][0] = f2tf32(v0); ah[mt][1] = f2tf32(v1);
                    ah[mt][2] = f2tf32(v2); ah[mt][3] = f2tf32(v3);
                }
            }
            const int bc = wn * 32 + (lane >> 2);
            const int bk = ks + (lane & 3);
#pragma unroll
            for (int nt = 0; nt < 4; nt++) {
                float v0 = Bs[bk    ][bc + nt * 8];
                float v1 = Bs[bk + 4][bc + nt * 8];
                if (PRECISE) {
                    tf32split(v0, bh[nt][0], bl[nt][0]);
                    tf32split(v1, bh[nt][1], bl[nt][1]);
                } else {
                    bh[nt][0] = f2tf32(v0); bh[nt][1] = f2tf32(v1);
                }
            }
#pragma unroll
            for (int mt = 0; mt < 2; mt++)
#pragma unroll
                for (int nt = 0; nt < 4; nt++) {
                    MMA4(acc[mt][nt], ah[mt][0], ah[mt][1], ah[mt][2], ah[mt][3],
                         bh[nt][0], bh[nt][1]);
                    if (PRECISE) {
                        MMA4(acc[mt][nt], ah[mt][0], ah[mt][1], ah[mt][2], ah[mt][3],
                             bl[nt][0], bl[nt][1]);
                        MMA4(acc[mt][nt], al[mt][0], al[mt][1], al[mt][2], al[mt][3],
                             bh[nt][0], bh[nt][1]);
                    }
                }
        }
        __syncthreads();
    }

#pragma unroll
    for (int mt = 0; mt < 2; mt++)
#pragma unroll
        for (int nt = 0; nt < 4; nt++)
#pragma unroll
            for (int i = 0; i < 4; i++) {
                int r = rowBase + wm * 32 + mt * 16 + (lane >> 2) + ((i >= 2) ? 8 : 0);
                int c = colBase + wn * 32 + nt * 8 + 2 * (lane & 3) + (i & 1);
                if (r < M && c < N) {
                    if (ATOMIC) {
                        atomicAdd(&C[(size_t)r * ldc + c], acc[mt][nt][i]);
                    } else {
                        float v = acc[mt][nt][i];
                        if (rowscale) v *= rowscale[r];
                        if (bias)     v += bias[c];
                        if (relu)     v = fmaxf(v, 0.f);
                        C[(size_t)r * ldc + c] = v;
                    }
                }
            }
}

// ---------------- GCN helper kernels ----------------
__global__ void k_deg_init(float* deg) {
    int i = blockIdx.x * blockDim.x + threadIdx.x;
    if (i < N_NODES) deg[i] = 1.f;
}
__global__ void k_deg_count(float* deg, const int* __restrict__ dst) {
    int e = blockIdx.x * blockDim.x + threadIdx.x;
    if (e < N_EDGES) atomicAdd(&deg[dst[e]], 1.f);
}
__global__ void k_rsqrt(float* d) {
    int i = blockIdx.x * blockDim.x + threadIdx.x;
    if (i < N_NODES) d[i] = rsqrtf(d[i]);
}

template <int VEC>
__global__ void k_scatter(float* __restrict__ OUT, const float* __restrict__ H,
                          int ld, const int* __restrict__ src, const int* __restrict__ dst,
                          const float* __restrict__ dinv, int fvec)
{
    int i = blockIdx.x * blockDim.x + threadIdx.x;
    int total = N_EDGES * fvec;
    if (i >= total) return;
    int e = i / fvec;
    int f = (i - e * fvec) * VEC;
    int s = src[e], d = dst[e];
    float nrm = dinv[s] * dinv[d];
    const float* hp = H + (size_t)s * ld + f;
    float* op = OUT + (size_t)d * ld + f;
    if (VEC == 4) {
        float4 h = *reinterpret_cast<const float4*>(hp);
        atomicAdd(op + 0, h.x * nrm);
        atomicAdd(op + 1, h.y * nrm);
        atomicAdd(op + 2, h.z * nrm);
        atomicAdd(op + 3, h.w * nrm);
    } else if (VEC == 2) {
        float2 h = *reinterpret_cast<const float2*>(hp);
        atomicAdd(op + 0, h.x * nrm);
        atomicAdd(op + 1, h.y * nrm);
    } else {
        atomicAdd(op, hp[0] * nrm);
    }
}

__global__ void k_finalize(float* __restrict__ OUT, const float* __restrict__ H,
                           int ld, const float* __restrict__ dinv,
                           const float* __restrict__ bias, int fo)
{
    int i = blockIdx.x * blockDim.x + threadIdx.x;
    int total = N_NODES * fo;
    if (i >= total) return;
    int node = i / fo;
    int f = i - node * fo;
    float di = dinv[node];
    size_t o = (size_t)node * ld + f;
    float v = OUT[o] + H[o] * (di * di) + bias[f];
    OUT[o] = fmaxf(v, 0.f);
}

__global__ void k_pool(float* __restrict__ pool, const float* __restrict__ X) {
    int i = blockIdx.x * blockDim.x + threadIdx.x;   // BATCH*312
    if (i >= BATCH * 312) return;
    int g = i / 312, f = i - g * 312;
    const float* p = X + (size_t)g * NPG * 312 + f;
    float m = p[0];
#pragma unroll 8
    for (int j = 1; j < NPG; j++) m = fmaxf(m, p[(size_t)j * 312]);
    pool[i] = m;
}

__global__ void k_rnorm(const float* __restrict__ cell, float* __restrict__ rn) {
    __shared__ float sm[256];
    int b = blockIdx.x;
    const float* row = cell + (size_t)b * 37261;
    float s = 0.f;
    for (int i = threadIdx.x; i < 37261; i += 256) { float v = row[i]; s += v * v; }
    sm[threadIdx.x] = s;
    __syncthreads();
    for (int off = 128; off > 0; off >>= 1) {
        if (threadIdx.x < off) sm[threadIdx.x] += sm[threadIdx.x + off];
        __syncthreads();
    }
    if (threadIdx.x == 0) rn[b] = 1.f / fmaxf(sqrtf(sm[0]), 1e-12f);
}

__global__ void k_cellepi(float* __restrict__ dst, const float* __restrict__ acc,
                          const float* __restrict__ rn, const float* __restrict__ bias)
{
    int i = blockIdx.x * blockDim.x + threadIdx.x;
    if (i >= BATCH * 512) return;
    int r = i >> 9, c = i & 511;
    dst[i] = fmaxf(acc[i] * rn[r] + bias[c], 0.f);
}

__global__ void k_out(const float* __restrict__ f2, const float* __restrict__ Wo,
                      const float* __restrict__ bo, float* __restrict__ out) {
    int i = blockIdx.x * blockDim.x + threadIdx.x;   // 2048
    if (i >= BATCH * 2) return;
    int b = i >> 1, o = i & 1;
    float s = bo[o];
    const float* fp = f2 + (size_t)b * 128;
#pragma unroll 8
    for (int k = 0; k < 128; k++) s += fp[k] * Wo[k * 2 + o];
    out[i] = s;
}

// ---------------- host orchestration ----------------
static inline int cdiv(int a, int b) { return (a + b - 1) / b; }
static inline dim3 ggrid(int M, int N) { return dim3(cdiv(N, 64), cdiv(M, 128), 1); }

static void run_branch(const float* x, const int* ei,
                       const float* Wc1, const float* bc1,
                       const float* Wc2, const float* bc2,
                       const float* Wc3, const float* bc3,
                       const float* Wg1, const float* bg1,
                       const float* Wg2, const float* bg2,
                       float* H_, float* A_, float* B_, float* dinv_,
                       float* pool_, float* p1_, float* xcDst)
{
    const int* src = ei;
    const int* dst = ei + N_EDGES;

    k_deg_init <<<cdiv(N_NODES, 256), 256>>>(dinv_);
    k_deg_count<<<cdiv(N_EDGES, 256), 256>>>(dinv_, dst);
    k_rsqrt    <<<cdiv(N_NODES, 256), 256>>>(dinv_);

    // conv1: 78 -> 78 (ld 80)
    gemm_tc<true,false><<<ggrid(N_NODES, 78), 256>>>(x, 78, Wc1, 78, H_, 80,
                                                     N_NODES, 78, 78, 78,
                                                     nullptr, nullptr, 0);
    cudaMemsetAsync(A_, 0, (size_t)N_NODES * 80 * sizeof(float));
    k_scatter<2><<<cdiv(N_EDGES * 39, 256), 256>>>(A_, H_, 80, src, dst, dinv_, 39);
    k_finalize  <<<cdiv(N_NODES * 78, 256), 256>>>(A_, H_, 80, dinv_, bc1, 78);

    // conv2: 78 -> 156
    gemm_tc<true,false><<<ggrid(N_NODES, 156), 256>>>(A_, 80, Wc2, 156, H_, 156,
                                                      N_NODES, 156, 78, 78,
                                                      nullptr, nullptr, 0);
    cudaMemsetAsync(B_, 0, (size_t)N_NODES * 156 * sizeof(float));
    k_scatter<4><<<cdiv(N_EDGES * 39, 256), 256>>>(B_, H_, 156, src, dst, dinv_, 39);
    k_finalize  <<<cdiv(N_NODES * 156, 256), 256>>>(B_, H_, 156, dinv_, bc2, 156);

    // conv3: 156 -> 312
    gemm_tc<true,false><<<ggrid(N_NODES, 312), 256>>>(B_, 156, Wc3, 312, H_, 312,
                                                      N_NODES, 312, 156, 156,
                                                      nullptr, nullptr, 0);
    cudaMemsetAsync(A_, 0, (size_t)N_NODES * 312 * sizeof(float));
    k_scatter<4><<<cdiv(N_EDGES * 78, 256), 256>>>(A_, H_, 312, src, dst, dinv_, 78);
    k_finalize  <<<cdiv(N_NODES * 312, 256), 256>>>(A_, H_, 312, dinv_, bc3, 312);

    // pool + MLP head
    k_pool<<<cdiv(BATCH * 312, 256), 256>>>(pool_, A_);
    gemm_tc<true,false><<<ggrid(BATCH, 156), 256>>>(pool_, 312, Wg1, 156, p1_, 156,
                                                    BATCH, 156, 312, 312, bg1, nullptr, 1);
    gemm_tc<true,false><<<ggrid(BATCH, 128), 256>>>(p1_, 156, Wg2, 128, xcDst, 384,
                                                    BATCH, 128, 156, 156, bg2, nullptr, 0);
}

extern "C" void kernel_launch(void* const* d_in, const int* in_sizes, int n_in,
                              void* d_out, int out_size)
{
    const float* x1   = (const float*)d_in[0];
    const int*   ei1  = (const int*)  d_in[1];
    const float* x2   = (const float*)d_in[3];
    const int*   ei2  = (const int*)  d_in[4];
    const float* cell = (const float*)d_in[6];
    const float *Wc1 = (const float*)d_in[7],  *bc1 = (const float*)d_in[8];
    const float *Wc2 = (const float*)d_in[9],  *bc2 = (const float*)d_in[10];
    const float *Wc3 = (const float*)d_in[11], *bc3 = (const float*)d_in[12];
    const float *Wg1 = (const float*)d_in[13], *bg1 = (const float*)d_in[14];
    const float *Wg2 = (const float*)d_in[15], *bg2 = (const float*)d_in[16];
    const float *Wr1 = (const float*)d_in[17], *br1 = (const float*)d_in[18];
    const float *Wr2 = (const float*)d_in[19], *br2 = (const float*)d_in[20];
    const float *Wr3 = (const float*)d_in[21], *br3 = (const float*)d_in[22];
    const float *Wf1 = (const float*)d_in[23], *bf1 = (const float*)d_in[24];
    const float *Wf2 = (const float*)d_in[25], *bf2 = (const float*)d_in[26];
    const float *Wo  = (const float*)d_in[27], *bo  = (const float*)d_in[28];

    float *H_, *A_, *B_, *dinv_, *pool_, *p1_, *acc_, *cv2_, *xc_, *f1_, *f2_, *rn_, *cv1_;
    cudaGetSymbolAddress((void**)&H_,   g_H);
    cudaGetSymbolAddress((void**)&A_,   g_A);
    cudaGetSymbolAddress((void**)&B_,   g_B2);
    cudaGetSymbolAddress((void**)&dinv_,g_dinv);
    cudaGetSymbolAddress((void**)&pool_,g_pool);
    cudaGetSymbolAddress((void**)&p1_,  g_p1);
    cudaGetSymbolAddress((void**)&acc_, g_acc);
    cudaGetSymbolAddress((void**)&cv1_, g_cv1);
    cudaGetSymbolAddress((void**)&cv2_, g_cv2);
    cudaGetSymbolAddress((void**)&xc_,  g_xc);
    cudaGetSymbolAddress((void**)&f1_,  g_f1);
    cudaGetSymbolAddress((void**)&f2_,  g_f2);
    cudaGetSymbolAddress((void**)&rn_,  g_rn);

    // ---- cell branch: rownorm fused via epilogue; big GEMM split-K=4 ----
    k_rnorm<<<BATCH, 256>>>(cell, rn_);
    cudaMemsetAsync(acc_, 0, (size_t)BATCH * 512 * sizeof(float));
    {
        int kChunk = cdiv(cdiv(37261, SPLITK), BK) * BK;   // 9344
        gemm_tc<true,true><<<dim3(8, 8, SPLITK), 256>>>(cell, 37261, Wr1, 512, acc_, 512,
                                                        BATCH, 512, 37261, kChunk,
                                                        nullptr, nullptr, 0);
    }
    k_cellepi<<<cdiv(BATCH * 512, 256), 256>>>(cv1_, acc_, rn_, br1);
    gemm_tc<true,false><<<ggrid(BATCH, 256), 256>>>(cv1_, 512, Wr2, 256, cv2_, 256,
                                                    BATCH, 256, 512, 512, br2, nullptr, 1);
    gemm_tc<true,false><<<ggrid(BATCH, 128), 256>>>(cv2_, 256, Wr3, 128, xc_ + 256, 384,
                                                    BATCH, 128, 256, 256, br3, nullptr, 0);

    // ---- drug branches (shared weights, per reference) ----
    run_branch(x1, ei1, Wc1, bc1, Wc2, bc2, Wc3, bc3, Wg1, bg1, Wg2, bg2,
               H_, A_, B_, dinv_, pool_, p1_, xc_ + 0);
    run_branch(x2, ei2, Wc1, bc1, Wc2, bc2, Wc3, bc3, Wg1, bg1, Wg2, bg2,
               H_, A_, B_, dinv_, pool_, p1_, xc_ + 128);

    // ---- fusion head ----
    gemm_tc<true,false><<<ggrid(BATCH, 512), 256>>>(xc_, 384, Wf1, 512, f1_, 512,
                                                    BATCH, 512, 384, 384, bf1, nullptr, 1);
    gemm_tc<true,false><<<ggrid(BATCH, 128), 256>>>(f1_, 512, Wf2, 128, f2_, 128,
                                                    BATCH, 128, 512, 512, bf2, nullptr, 1);
    k_out<<<cdiv(BATCH * 2, 256), 256>>>(f2_, Wo, bo, (float*)d_out);
}

// round 3
// speedup vs baseline: 3.9861x; 1.2061x over previous
#include <cuda_runtime.h>
#include <cuda_fp16.h>
#include <cstdint>
#include <cstddef>

#define N_NODES 40960
#define N_STACK (2 * N_NODES)
#define N_EDGES 131072
#define BATCH   1024
#define NPG     40
#define BK      32
#define SPLITK  8

// ---------------- scratch ----------------
__device__ float g_H [N_STACK * 312];
__device__ float g_A [N_STACK * 312];
__device__ float g_B2[N_STACK * 312];
__device__ float g_dinv[N_STACK];
__device__ float g_pool[2 * BATCH * 312];
__device__ float g_p1  [2 * BATCH * 156];
__device__ float g_gt  [2 * BATCH * 128];
__device__ float g_acc[BATCH * 512];
__device__ float g_cv1[BATCH * 512];
__device__ float g_cv2[BATCH * 256];
__device__ float g_xc [BATCH * 384];
__device__ float g_f1 [BATCH * 512];
__device__ float g_f2 [BATCH * 128];
__device__ float g_rn [BATCH];

// ---------------- fp16 hi/lo GEMM ----------------
__device__ __forceinline__ void h2split(float v, __half& h, __half& l) {
    h = __float2half_rn(v);
    l = __float2half_rn(v - __half2float(h));
}

#define MMA16(d, a, b)                                                           \
    asm volatile(                                                                \
        "mma.sync.aligned.m16n8k16.row.col.f32.f16.f16.f32 "                     \
        "{%0,%1,%2,%3},{%4,%5,%6,%7},{%8,%9},{%0,%1,%2,%3};"                     \
        : "+f"((d)[0]), "+f"((d)[1]), "+f"((d)[2]), "+f"((d)[3])                 \
        : "r"((a)[0]), "r"((a)[1]), "r"((a)[2]), "r"((a)[3]),                    \
          "r"((b)[0]), "r"((b)[1]))

// C[M,N] = A[M,K] @ B[K,N], row-major. Tile 128x64x32, 8 warps (4x2), warp 32x32.
// fp16 hi/lo 3-pass (~fp32 accuracy). Register-prefetch pipeline.
template<bool ATOMIC>
__global__ void __launch_bounds__(256, 2) gemm_h2(
    const float* __restrict__ A, int lda,
    const float* __restrict__ B, int ldb,
    float* __restrict__ C, int ldc,
    int M, int N, int K, int kChunk,
    const float* __restrict__ bias,
    const float* __restrict__ rowscale,
    int relu)
{
    __shared__ __align__(16) __half As_h[128][34];
    __shared__ __align__(16) __half As_l[128][34];
    __shared__ __align__(16) __half Bs_h[64][34];
    __shared__ __align__(16) __half Bs_l[64][34];

    const int tid  = threadIdx.x;
    const int lane = tid & 31;
    const int wid  = tid >> 5;
    const int wm   = wid & 3;
    const int wn   = wid >> 2;
    const int g    = lane >> 2;
    const int tg2  = (lane & 3) * 2;
    const int rowBase = blockIdx.y * 128;
    const int colBase = blockIdx.x * 64;
    const int kStart  = blockIdx.z * kChunk;
    const int kEnd    = min(K, kStart + kChunk);

    float acc[2][4][4];
#pragma unroll
    for (int a = 0; a < 2; a++)
#pragma unroll
        for (int b = 0; b < 4; b++)
#pragma unroll
            for (int i = 0; i < 4; i++) acc[a][b][i] = 0.f;

    float ra[16], rb[8];
    auto loadA = [&](int k0) {
#pragma unroll
        for (int i = 0; i < 16; i++) {
            int idx = tid + i * 256;
            int r = idx >> 5, c = idx & 31;
            int gr = rowBase + r, gc = k0 + c;
            ra[i] = (gr < M && gc < kEnd) ? A[(size_t)gr * lda + gc] : 0.f;
        }
    };
    auto loadB = [&](int k0) {
#pragma unroll
        for (int i = 0; i < 8; i++) {
            int idx = tid + i * 256;
            int k = idx >> 6, c = idx & 63;
            int gk = k0 + k, gc = colBase + c;
            rb[i] = (gk < kEnd && gc < N) ? B[(size_t)gk * ldb + gc] : 0.f;
        }
    };

    loadA(kStart);
    loadB(kStart);

    for (int k0 = kStart; k0 < kEnd; k0 += BK) {
#pragma unroll
        for (int i = 0; i < 16; i++) {
            int idx = tid + i * 256;
            int r = idx >> 5, c = idx & 31;
            h2split(ra[i], As_h[r][c], As_l[r][c]);
        }
#pragma unroll
        for (int i = 0; i < 8; i++) {
            int idx = tid + i * 256;
            int k = idx >> 6, c = idx & 63;
            h2split(rb[i], Bs_h[c][k], Bs_l[c][k]);   // transposed: [n][k]
        }
        __syncthreads();

        if (k0 + BK < kEnd) { loadA(k0 + BK); loadB(k0 + BK); }

#pragma unroll
        for (int ks = 0; ks < 2; ks++) {
            const int kb = ks * 16;
            unsigned ah[2][4], al[2][4], bh[4][2], bl[4][2];
#pragma unroll
            for (int mt = 0; mt < 2; mt++) {
                int r0 = wm * 32 + mt * 16 + g;
                ah[mt][0] = *(const unsigned*)&As_h[r0    ][kb + tg2];
                ah[mt][1] = *(const unsigned*)&As_h[r0 + 8][kb + tg2];
                ah[mt][2] = *(const unsigned*)&As_h[r0    ][kb + 8 + tg2];
                ah[mt][3] = *(const unsigned*)&As_h[r0 + 8][kb + 8 + tg2];
                al[mt][0] = *(const unsigned*)&As_l[r0    ][kb + tg2];
                al[mt][1] = *(const unsigned*)&As_l[r0 + 8][kb + tg2];
                al[mt][2] = *(const unsigned*)&As_l[r0    ][kb + 8 + tg2];
                al[mt][3] = *(const unsigned*)&As_l[r0 + 8][kb + 8 + tg2];
            }
#pragma unroll
            for (int nt = 0; nt < 4; nt++) {
                int c0 = wn * 32 + nt * 8 + g;
                bh[nt][0] = *(const unsigned*)&Bs_h[c0][kb + tg2];
                bh[nt][1] = *(const unsigned*)&Bs_h[c0][kb + 8 + tg2];
                bl[nt][0] = *(const unsigned*)&Bs_l[c0][kb + tg2];
                bl[nt][1] = *(const unsigned*)&Bs_l[c0][kb + 8 + tg2];
            }
#pragma unroll
            for (int mt = 0; mt < 2; mt++)
#pragma unroll
                for (int nt = 0; nt < 4; nt++) {
                    MMA16(acc[mt][nt], ah[mt], bh[nt]);
                    MMA16(acc[mt][nt], ah[mt], bl[nt]);
                    MMA16(acc[mt][nt], al[mt], bh[nt]);
                }
        }
        __syncthreads();
    }

#pragma unroll
    for (int mt = 0; mt < 2; mt++)
#pragma unroll
        for (int nt = 0; nt < 4; nt++)
#pragma unroll
            for (int i = 0; i < 4; i++) {
                int r = rowBase + wm * 32 + mt * 16 + g + ((i >= 2) ? 8 : 0);
                int c = colBase + wn * 32 + nt * 8 + tg2 + (i & 1);
                if (r < M && c < N) {
                    if (ATOMIC) {
                        atomicAdd(&C[(size_t)r * ldc + c], acc[mt][nt][i]);
                    } else {
                        float v = acc[mt][nt][i];
                        if (rowscale) v *= rowscale[r];
                        if (bias)     v += bias[c];
                        if (relu)     v = fmaxf(v, 0.f);
                        C[(size_t)r * ldc + c] = v;
                    }
                }
            }
}

// ---------------- GCN helpers (stacked branches) ----------------
__global__ void k_deg_init(float* deg) {
    int i = blockIdx.x * blockDim.x + threadIdx.x;
    if (i < N_STACK) deg[i] = 1.f;
}
__global__ void k_deg_count2(float* deg, const int* __restrict__ d1,
                             const int* __restrict__ d2) {
    int e = blockIdx.x * blockDim.x + threadIdx.x;
    if (e >= 2 * N_EDGES) return;
    int d = (e < N_EDGES) ? d1[e] : (d2[e - N_EDGES] + N_NODES);
    atomicAdd(&deg[d], 1.f);
}
__global__ void k_rsqrt(float* d) {
    int i = blockIdx.x * blockDim.x + threadIdx.x;
    if (i < N_STACK) d[i] = rsqrtf(d[i]);
}

template <int VEC>
__global__ void k_scatter2(float* __restrict__ OUT, const float* __restrict__ H,
                           int ld,
                           const int* __restrict__ s1, const int* __restrict__ d1,
                           const int* __restrict__ s2, const int* __restrict__ d2,
                           const float* __restrict__ dinv, int fvec)
{
    long long i = (long long)blockIdx.x * blockDim.x + threadIdx.x;
    long long total = (long long)2 * N_EDGES * fvec;
    if (i >= total) return;
    int e = (int)(i / fvec);
    int f = (int)(i - (long long)e * fvec) * VEC;
    int s, d;
    if (e < N_EDGES) { s = s1[e]; d = d1[e]; }
    else             { s = s2[e - N_EDGES] + N_NODES; d = d2[e - N_EDGES] + N_NODES; }
    float nrm = dinv[s] * dinv[d];
    const float* hp = H + (size_t)s * ld + f;
    float* op = OUT + (size_t)d * ld + f;
    if (VEC == 4) {
        float4 h = *reinterpret_cast<const float4*>(hp);
        atomicAdd(op + 0, h.x * nrm);
        atomicAdd(op + 1, h.y * nrm);
        atomicAdd(op + 2, h.z * nrm);
        atomicAdd(op + 3, h.w * nrm);
    } else {
        float2 h = *reinterpret_cast<const float2*>(hp);
        atomicAdd(op + 0, h.x * nrm);
        atomicAdd(op + 1, h.y * nrm);
    }
}

__global__ void k_finalize(float* __restrict__ OUT, const float* __restrict__ H,
                           int ld, const float* __restrict__ dinv,
                           const float* __restrict__ bias, int fo)
{
    long long i = (long long)blockIdx.x * blockDim.x + threadIdx.x;
    long long total = (long long)N_STACK * fo;
    if (i >= total) return;
    int node = (int)(i / fo);
    int f = (int)(i - (long long)node * fo);
    float di = dinv[node];
    size_t o = (size_t)node * ld + f;
    float v = OUT[o] + H[o] * (di * di) + bias[f];
    OUT[o] = fmaxf(v, 0.f);
}

__global__ void k_pool(float* __restrict__ pool, const float* __restrict__ X) {
    int i = blockIdx.x * blockDim.x + threadIdx.x;   // 2*BATCH*312
    if (i >= 2 * BATCH * 312) return;
    int gg = i / 312, f = i - gg * 312;
    const float* p = X + (size_t)gg * NPG * 312 + f;
    float m = p[0];
#pragma unroll 8
    for (int j = 1; j < NPG; j++) m = fmaxf(m, p[(size_t)j * 312]);
    pool[i] = m;
}

__global__ void k_xcpack(float* __restrict__ xc, const float* __restrict__ gt) {
    int i = blockIdx.x * blockDim.x + threadIdx.x;   // BATCH*256
    if (i >= BATCH * 256) return;
    int b = i >> 8, c = i & 255;
    float v = (c < 128) ? gt[(size_t)b * 128 + c]
                        : gt[(size_t)(BATCH + b) * 128 + (c - 128)];
    xc[(size_t)b * 384 + c] = v;
}

__global__ void k_rnorm(const float* __restrict__ cell, float* __restrict__ rn) {
    __shared__ float sm[256];
    int b = blockIdx.x;
    const float* row = cell + (size_t)b * 37261;
    float s = 0.f;
    for (int i = threadIdx.x; i < 37261; i += 256) { float v = row[i]; s += v * v; }
    sm[threadIdx.x] = s;
    __syncthreads();
    for (int off = 128; off > 0; off >>= 1) {
        if (threadIdx.x < off) sm[threadIdx.x] += sm[threadIdx.x + off];
        __syncthreads();
    }
    if (threadIdx.x == 0) rn[b] = 1.f / fmaxf(sqrtf(sm[0]), 1e-12f);
}

__global__ void k_cellepi(float* __restrict__ dst, const float* __restrict__ acc,
                          const float* __restrict__ rn, const float* __restrict__ bias)
{
    int i = blockIdx.x * blockDim.x + threadIdx.x;
    if (i >= BATCH * 512) return;
    int r = i >> 9, c = i & 511;
    dst[i] = fmaxf(acc[i] * rn[r] + bias[c], 0.f);
}

__global__ void k_out(const float* __restrict__ f2, const float* __restrict__ Wo,
                      const float* __restrict__ bo, float* __restrict__ out) {
    int i = blockIdx.x * blockDim.x + threadIdx.x;
    if (i >= BATCH * 2) return;
    int b = i >> 1, o = i & 1;
    float s = bo[o];
    const float* fp = f2 + (size_t)b * 128;
#pragma unroll 8
    for (int k = 0; k < 128; k++) s += fp[k] * Wo[k * 2 + o];
    out[i] = s;
}

// ---------------- host ----------------
static inline int cdiv(int a, int b) { return (a + b - 1) / b; }
static inline dim3 ggrid(int M, int N) { return dim3(cdiv(N, 64), cdiv(M, 128), 1); }

extern "C" void kernel_launch(void* const* d_in, const int* in_sizes, int n_in,
                              void* d_out, int out_size)
{
    const float* x1   = (const float*)d_in[0];
    const int*   ei1  = (const int*)  d_in[1];
    const float* x2   = (const float*)d_in[3];
    const int*   ei2  = (const int*)  d_in[4];
    const float* cell = (const float*)d_in[6];
    const float *Wc1 = (const float*)d_in[7],  *bc1 = (const float*)d_in[8];
    const float *Wc2 = (const float*)d_in[9],  *bc2 = (const float*)d_in[10];
    const float *Wc3 = (const float*)d_in[11], *bc3 = (const float*)d_in[12];
    const float *Wg1 = (const float*)d_in[13], *bg1 = (const float*)d_in[14];
    const float *Wg2 = (const float*)d_in[15], *bg2 = (const float*)d_in[16];
    const float *Wr1 = (const float*)d_in[17], *br1 = (const float*)d_in[18];
    const float *Wr2 = (const float*)d_in[19], *br2 = (const float*)d_in[20];
    const float *Wr3 = (const float*)d_in[21], *br3 = (const float*)d_in[22];
    const float *Wf1 = (const float*)d_in[23], *bf1 = (const float*)d_in[24];
    const float *Wf2 = (const float*)d_in[25], *bf2 = (const float*)d_in[26];
    const float *Wo  = (const float*)d_in[27], *bo  = (const float*)d_in[28];

    const int* s1 = ei1;  const int* d1 = ei1 + N_EDGES;
    const int* s2 = ei2;  const int* d2 = ei2 + N_EDGES;

    float *H_, *A_, *B_, *dinv_, *pool_, *p1_, *gt_, *acc_, *cv1_, *cv2_, *xc_, *f1_, *f2_, *rn_;
    cudaGetSymbolAddress((void**)&H_,    g_H);
    cudaGetSymbolAddress((void**)&A_,    g_A);
    cudaGetSymbolAddress((void**)&B_,    g_B2);
    cudaGetSymbolAddress((void**)&dinv_, g_dinv);
    cudaGetSymbolAddress((void**)&pool_, g_pool);
    cudaGetSymbolAddress((void**)&p1_,   g_p1);
    cudaGetSymbolAddress((void**)&gt_,   g_gt);
    cudaGetSymbolAddress((void**)&acc_,  g_acc);
    cudaGetSymbolAddress((void**)&cv1_,  g_cv1);
    cudaGetSymbolAddress((void**)&cv2_,  g_cv2);
    cudaGetSymbolAddress((void**)&xc_,   g_xc);
    cudaGetSymbolAddress((void**)&f1_,   g_f1);
    cudaGetSymbolAddress((void**)&f2_,   g_f2);
    cudaGetSymbolAddress((void**)&rn_,   g_rn);

    // ---- cell branch: split-K big GEMM, rownorm fused in epilogue ----
    k_rnorm<<<BATCH, 256>>>(cell, rn_);
    cudaMemsetAsync(acc_, 0, (size_t)BATCH * 512 * sizeof(float));
    {
        int kChunk = cdiv(cdiv(37261, SPLITK), BK) * BK;
        gemm_h2<true><<<dim3(8, 8, SPLITK), 256>>>(cell, 37261, Wr1, 512, acc_, 512,
                                                   BATCH, 512, 37261, kChunk,
                                                   nullptr, nullptr, 0);
    }
    k_cellepi<<<cdiv(BATCH * 512, 256), 256>>>(cv1_, acc_, rn_, br1);
    gemm_h2<false><<<ggrid(BATCH, 256), 256>>>(cv1_, 512, Wr2, 256, cv2_, 256,
                                               BATCH, 256, 512, 512, br2, nullptr, 1);
    gemm_h2<false><<<ggrid(BATCH, 128), 256>>>(cv2_, 256, Wr3, 128, xc_ + 256, 384,
                                               BATCH, 128, 256, 256, br3, nullptr, 0);

    // ---- stacked drug branches ----
    k_deg_init  <<<cdiv(N_STACK, 256), 256>>>(dinv_);
    k_deg_count2<<<cdiv(2 * N_EDGES, 256), 256>>>(dinv_, d1, d2);
    k_rsqrt     <<<cdiv(N_STACK, 256), 256>>>(dinv_);

    // conv1: 78 -> 78 (ld 80)
    gemm_h2<false><<<ggrid(N_NODES, 78), 256>>>(x1, 78, Wc1, 78, H_, 80,
                                                N_NODES, 78, 78, 78, nullptr, nullptr, 0);
    gemm_h2<false><<<ggrid(N_NODES, 78), 256>>>(x2, 78, Wc1, 78, H_ + (size_t)N_NODES * 80, 80,
                                                N_NODES, 78, 78, 78, nullptr, nullptr, 0);
    cudaMemsetAsync(A_, 0, (size_t)N_STACK * 80 * sizeof(float));
    k_scatter2<2><<<cdiv(2 * N_EDGES * 39, 256), 256>>>(A_, H_, 80, s1, d1, s2, d2, dinv_, 39);
    k_finalize   <<<cdiv(N_STACK * 78, 256), 256>>>(A_, H_, 80, dinv_, bc1, 78);

    // conv2: 78 -> 156
    gemm_h2<false><<<ggrid(N_STACK, 156), 256>>>(A_, 80, Wc2, 156, H_, 156,
                                                 N_STACK, 156, 78, 78, nullptr, nullptr, 0);
    cudaMemsetAsync(B_, 0, (size_t)N_STACK * 156 * sizeof(float));
    k_scatter2<4><<<cdiv(2 * N_EDGES * 39, 256), 256>>>(B_, H_, 156, s1, d1, s2, d2, dinv_, 39);
    k_finalize   <<<cdiv(N_STACK * 156, 256), 256>>>(B_, H_, 156, dinv_, bc2, 156);

    // conv3: 156 -> 312
    gemm_h2<false><<<ggrid(N_STACK, 312), 256>>>(B_, 156, Wc3, 312, H_, 312,
                                                 N_STACK, 312, 156, 156, nullptr, nullptr, 0);
    cudaMemsetAsync(A_, 0, (size_t)N_STACK * 312 * sizeof(float));
    k_scatter2<4><<<cdiv(2 * N_EDGES * 78, 256), 256>>>(A_, H_, 312, s1, d1, s2, d2, dinv_, 78);
    k_finalize   <<<cdiv(N_STACK * 312, 256), 256>>>(A_, H_, 312, dinv_, bc3, 312);

    // pool + shared MLP head over both branches at once (M = 2048)
    k_pool<<<cdiv(2 * BATCH * 312, 256), 256>>>(pool_, A_);
    gemm_h2<false><<<ggrid(2 * BATCH, 156), 256>>>(pool_, 312, Wg1, 156, p1_, 156,
                                                   2 * BATCH, 156, 312, 312, bg1, nullptr, 1);
    gemm_h2<false><<<ggrid(2 * BATCH, 128), 256>>>(p1_, 156, Wg2, 128, gt_, 128,
                                                   2 * BATCH, 128, 156, 156, bg2, nullptr, 0);
    k_xcpack<<<cdiv(BATCH * 256, 256), 256>>>(xc_, gt_);

    // ---- fusion head ----
    gemm_h2<false><<<ggrid(BATCH, 512), 256>>>(xc_, 384, Wf1, 512, f1_, 512,
                                               BATCH, 512, 384, 384, bf1, nullptr, 1);
    gemm_h2<false><<<ggrid(BATCH, 128), 256>>>(f1_, 512, Wf2, 128, f2_, 128,
                                               BATCH, 128, 512, 512, bf2, nullptr, 1);
    k_out<<<cdiv(BATCH * 2, 256), 256>>>(f2_, Wo, bo, (float*)d_out);
}

// round 4
// speedup vs baseline: 4.5898x; 1.1515x over previous
#include <cuda_runtime.h>
#include <cuda_fp16.h>
#include <cstdint>
#include <cstddef>

#define N_NODES 40960
#define N_STACK (2 * N_NODES)
#define N_EDGES 131072
#define E2      (2 * N_EDGES)
#define BATCH   1024
#define NPG     40
#define BK      32
#define SPLITK  8

// ---------------- scratch ----------------
__device__ float g_H [N_STACK * 312];
__device__ float g_A [N_STACK * 156];
__device__ float g_B2[N_STACK * 156];
__device__ float g_dinv[N_STACK];
__device__ int   g_cnt[N_STACK];
__device__ int   g_rowptr[N_STACK + 1];
__device__ int   g_cursor[N_STACK];
__device__ int   g_csrc[E2];
__device__ float g_pool[2 * BATCH * 312];
__device__ float g_p1  [2 * BATCH * 156];
__device__ float g_gt  [2 * BATCH * 128];
__device__ float g_acc[BATCH * 512];
__device__ float g_cv1[BATCH * 512];
__device__ float g_cv2[BATCH * 256];
__device__ float g_xc [BATCH * 384];
__device__ float g_f1 [BATCH * 512];
__device__ float g_f2 [BATCH * 128];
__device__ float g_rn [BATCH];

// ---------------- fp16 hi/lo GEMM ----------------
__device__ __forceinline__ void h2split(float v, __half& h, __half& l) {
    h = __float2half_rn(v);
    l = __float2half_rn(v - __half2float(h));
}

#define MMA16(d, a, b)                                                           \
    asm volatile(                                                                \
        "mma.sync.aligned.m16n8k16.row.col.f32.f16.f16.f32 "                     \
        "{%0,%1,%2,%3},{%4,%5,%6,%7},{%8,%9},{%0,%1,%2,%3};"                     \
        : "+f"((d)[0]), "+f"((d)[1]), "+f"((d)[2]), "+f"((d)[3])                 \
        : "r"((a)[0]), "r"((a)[1]), "r"((a)[2]), "r"((a)[3]),                    \
          "r"((b)[0]), "r"((b)[1]))

template<bool ATOMIC>
__global__ void __launch_bounds__(256, 2) gemm_h2(
    const float* __restrict__ A, int lda,
    const float* __restrict__ B, int ldb,
    float* __restrict__ C, int ldc,
    int M, int N, int K, int kChunk,
    const float* __restrict__ bias,
    const float* __restrict__ rowscale,
    int relu)
{
    __shared__ __align__(16) __half As_h[128][34];
    __shared__ __align__(16) __half As_l[128][34];
    __shared__ __align__(16) __half Bs_h[64][34];
    __shared__ __align__(16) __half Bs_l[64][34];

    const int tid  = threadIdx.x;
    const int lane = tid & 31;
    const int wid  = tid >> 5;
    const int wm   = wid & 3;
    const int wn   = wid >> 2;
    const int g    = lane >> 2;
    const int tg2  = (lane & 3) * 2;
    const int rowBase = blockIdx.y * 128;
    const int colBase = blockIdx.x * 64;
    const int kStart  = blockIdx.z * kChunk;
    const int kEnd    = min(K, kStart + kChunk);

    float acc[2][4][4];
#pragma unroll
    for (int a = 0; a < 2; a++)
#pragma unroll
        for (int b = 0; b < 4; b++)
#pragma unroll
            for (int i = 0; i < 4; i++) acc[a][b][i] = 0.f;

    float ra[16], rb[8];
    auto loadA = [&](int k0) {
#pragma unroll
        for (int i = 0; i < 16; i++) {
            int idx = tid + i * 256;
            int r = idx >> 5, c = idx & 31;
            int gr = rowBase + r, gc = k0 + c;
            ra[i] = (gr < M && gc < kEnd) ? A[(size_t)gr * lda + gc] : 0.f;
        }
    };
    auto loadB = [&](int k0) {
#pragma unroll
        for (int i = 0; i < 8; i++) {
            int idx = tid + i * 256;
            int k = idx >> 6, c = idx & 63;
            int gk = k0 + k, gc = colBase + c;
            rb[i] = (gk < kEnd && gc < N) ? B[(size_t)gk * ldb + gc] : 0.f;
        }
    };

    loadA(kStart);
    loadB(kStart);

    for (int k0 = kStart; k0 < kEnd; k0 += BK) {
#pragma unroll
        for (int i = 0; i < 16; i++) {
            int idx = tid + i * 256;
            int r = idx >> 5, c = idx & 31;
            h2split(ra[i], As_h[r][c], As_l[r][c]);
        }
#pragma unroll
        for (int i = 0; i < 8; i++) {
            int idx = tid + i * 256;
            int k = idx >> 6, c = idx & 63;
            h2split(rb[i], Bs_h[c][k], Bs_l[c][k]);
        }
        __syncthreads();

        if (k0 + BK < kEnd) { loadA(k0 + BK); loadB(k0 + BK); }

#pragma unroll
        for (int ks = 0; ks < 2; ks++) {
            const int kb = ks * 16;
            unsigned ah[2][4], al[2][4], bh[4][2], bl[4][2];
#pragma unroll
            for (int mt = 0; mt < 2; mt++) {
                int r0 = wm * 32 + mt * 16 + g;
                ah[mt][0] = *(const unsigned*)&As_h[r0    ][kb + tg2];
                ah[mt][1] = *(const unsigned*)&As_h[r0 + 8][kb + tg2];
                ah[mt][2] = *(const unsigned*)&As_h[r0    ][kb + 8 + tg2];
                ah[mt][3] = *(const unsigned*)&As_h[r0 + 8][kb + 8 + tg2];
                al[mt][0] = *(const unsigned*)&As_l[r0    ][kb + tg2];
                al[mt][1] = *(const unsigned*)&As_l[r0 + 8][kb + tg2];
                al[mt][2] = *(const unsigned*)&As_l[r0    ][kb + 8 + tg2];
                al[mt][3] = *(const unsigned*)&As_l[r0 + 8][kb + 8 + tg2];
            }
#pragma unroll
            for (int nt = 0; nt < 4; nt++) {
                int c0 = wn * 32 + nt * 8 + g;
                bh[nt][0] = *(const unsigned*)&Bs_h[c0][kb + tg2];
                bh[nt][1] = *(const unsigned*)&Bs_h[c0][kb + 8 + tg2];
                bl[nt][0] = *(const unsigned*)&Bs_l[c0][kb + tg2];
                bl[nt][1] = *(const unsigned*)&Bs_l[c0][kb + 8 + tg2];
            }
#pragma unroll
            for (int mt = 0; mt < 2; mt++)
#pragma unroll
                for (int nt = 0; nt < 4; nt++) {
                    MMA16(acc[mt][nt], ah[mt], bh[nt]);
                    MMA16(acc[mt][nt], ah[mt], bl[nt]);
                    MMA16(acc[mt][nt], al[mt], bh[nt]);
                }
        }
        __syncthreads();
    }

#pragma unroll
    for (int mt = 0; mt < 2; mt++)
#pragma unroll
        for (int nt = 0; nt < 4; nt++)
#pragma unroll
            for (int i = 0; i < 4; i++) {
                int r = rowBase + wm * 32 + mt * 16 + g + ((i >= 2) ? 8 : 0);
                int c = colBase + wn * 32 + nt * 8 + tg2 + (i & 1);
                if (r < M && c < N) {
                    if (ATOMIC) {
                        atomicAdd(&C[(size_t)r * ldc + c], acc[mt][nt][i]);
                    } else {
                        float v = acc[mt][nt][i];
                        if (rowscale) v *= rowscale[r];
                        if (bias)     v += bias[c];
                        if (relu)     v = fmaxf(v, 0.f);
                        C[(size_t)r * ldc + c] = v;
                    }
                }
            }
}

// ---------------- CSR build ----------------
__global__ void k_hist(int* __restrict__ cnt, const int* __restrict__ d1,
                       const int* __restrict__ d2) {
    int e = blockIdx.x * blockDim.x + threadIdx.x;
    if (e >= E2) return;
    int d = (e < N_EDGES) ? d1[e] : (d2[e - N_EDGES] + N_NODES);
    atomicAdd(&cnt[d], 1);
}
__global__ void k_dinv(float* __restrict__ dinv, const int* __restrict__ cnt) {
    int i = blockIdx.x * blockDim.x + threadIdx.x;
    if (i < N_STACK) dinv[i] = rsqrtf((float)cnt[i] + 1.f);
}
// single-block exclusive scan over N_STACK counts -> rowptr & cursor
__global__ void __launch_bounds__(1024) k_scan(const int* __restrict__ cnt,
                                               int* __restrict__ rowptr,
                                               int* __restrict__ cursor) {
    __shared__ int sm[1024];
    const int CH = N_STACK / 1024;   // 80
    int t = threadIdx.x;
    int base = t * CH;
    int s = 0;
#pragma unroll 4
    for (int j = 0; j < CH; j++) s += cnt[base + j];
    sm[t] = s;
    __syncthreads();
    // Hillis-Steele inclusive scan
    for (int off = 1; off < 1024; off <<= 1) {
        int v = (t >= off) ? sm[t - off] : 0;
        __syncthreads();
        sm[t] += v;
        __syncthreads();
    }
    int run = (t > 0) ? sm[t - 1] : 0;
    for (int j = 0; j < CH; j++) {
        rowptr[base + j] = run;
        cursor[base + j] = run;
        run += cnt[base + j];
    }
    if (t == 1023) rowptr[N_STACK] = run;
}
__global__ void k_bucket(int* __restrict__ cursor, int* __restrict__ csrc,
                         const int* __restrict__ s1, const int* __restrict__ d1,
                         const int* __restrict__ s2, const int* __restrict__ d2) {
    int e = blockIdx.x * blockDim.x + threadIdx.x;
    if (e >= E2) return;
    int s, d;
    if (e < N_EDGES) { s = s1[e]; d = d1[e]; }
    else             { s = s2[e - N_EDGES] + N_NODES; d = d2[e - N_EDGES] + N_NODES; }
    int pos = atomicAdd(&cursor[d], 1);
    csrc[pos] = s;
}

// ---------------- CSR gather aggregation (input-space) ----------------
// out[n] = dinv[n] * ( sum_{s in N(n)} dinv[s]*X[s]  +  dinv[n]*X[n] )
template <int VEC>
__global__ void k_gather(float* __restrict__ out, int ldo,
                         const float* __restrict__ X1, const float* __restrict__ X2,
                         int ldin, int fvec,
                         const int* __restrict__ rowptr, const int* __restrict__ csrc,
                         const float* __restrict__ dinv)
{
    long long i = (long long)blockIdx.x * blockDim.x + threadIdx.x;
    if (i >= (long long)N_STACK * fvec) return;
    int n = (int)(i / fvec);
    int f = (int)(i - (long long)n * fvec) * VEC;

    const float* Xn = (n < N_NODES) ? X1 + (size_t)n * ldin
                                    : X2 + (size_t)(n - N_NODES) * ldin;
    float dn = dinv[n];
    int b0 = rowptr[n], b1 = rowptr[n + 1];

    if (VEC == 4) {
        float4 v = *reinterpret_cast<const float4*>(Xn + f);
        float ax = v.x * dn, ay = v.y * dn, az = v.z * dn, aw = v.w * dn;
        for (int j = b0; j < b1; j++) {
            int s = csrc[j];
            const float* Xs = (s < N_NODES) ? X1 + (size_t)s * ldin
                                            : X2 + (size_t)(s - N_NODES) * ldin;
            float ds = dinv[s];
            float4 u = *reinterpret_cast<const float4*>(Xs + f);
            ax += u.x * ds; ay += u.y * ds; az += u.z * ds; aw += u.w * ds;
        }
        float4 o; o.x = ax * dn; o.y = ay * dn; o.z = az * dn; o.w = aw * dn;
        *reinterpret_cast<float4*>(out + (size_t)n * ldo + f) = o;
    } else {
        float2 v = *reinterpret_cast<const float2*>(Xn + f);
        float ax = v.x * dn, ay = v.y * dn;
        for (int j = b0; j < b1; j++) {
            int s = csrc[j];
            const float* Xs = (s < N_NODES) ? X1 + (size_t)s * ldin
                                            : X2 + (size_t)(s - N_NODES) * ldin;
            float ds = dinv[s];
            float2 u = *reinterpret_cast<const float2*>(Xs + f);
            ax += u.x * ds; ay += u.y * ds;
        }
        float2 o; o.x = ax * dn; o.y = ay * dn;
        *reinterpret_cast<float2*>(out + (size_t)n * ldo + f) = o;
    }
}

// ---------------- misc ----------------
__global__ void k_pool(float* __restrict__ pool, const float* __restrict__ X) {
    int i = blockIdx.x * blockDim.x + threadIdx.x;
    if (i >= 2 * BATCH * 312) return;
    int gg = i / 312, f = i - gg * 312;
    const float* p = X + (size_t)gg * NPG * 312 + f;
    float m = p[0];
#pragma unroll 8
    for (int j = 1; j < NPG; j++) m = fmaxf(m, p[(size_t)j * 312]);
    pool[i] = m;
}

__global__ void k_xcpack(float* __restrict__ xc, const float* __restrict__ gt) {
    int i = blockIdx.x * blockDim.x + threadIdx.x;
    if (i >= BATCH * 256) return;
    int b = i >> 8, c = i & 255;
    float v = (c < 128) ? gt[(size_t)b * 128 + c]
                        : gt[(size_t)(BATCH + b) * 128 + (c - 128)];
    xc[(size_t)b * 384 + c] = v;
}

__global__ void k_rnorm(const float* __restrict__ cell, float* __restrict__ rn) {
    __shared__ float sm[256];
    int b = blockIdx.x;
    const float* row = cell + (size_t)b * 37261;
    float s = 0.f;
    for (int i = threadIdx.x; i < 37261; i += 256) { float v = row[i]; s += v * v; }
    sm[threadIdx.x] = s;
    __syncthreads();
    for (int off = 128; off > 0; off >>= 1) {
        if (threadIdx.x < off) sm[threadIdx.x] += sm[threadIdx.x + off];
        __syncthreads();
    }
    if (threadIdx.x == 0) rn[b] = 1.f / fmaxf(sqrtf(sm[0]), 1e-12f);
}

__global__ void k_cellepi(float* __restrict__ dst, const float* __restrict__ acc,
                          const float* __restrict__ rn, const float* __restrict__ bias)
{
    int i = blockIdx.x * blockDim.x + threadIdx.x;
    if (i >= BATCH * 512) return;
    int r = i >> 9, c = i & 511;
    dst[i] = fmaxf(acc[i] * rn[r] + bias[c], 0.f);
}

__global__ void k_out(const float* __restrict__ f2, const float* __restrict__ Wo,
                      const float* __restrict__ bo, float* __restrict__ out) {
    int i = blockIdx.x * blockDim.x + threadIdx.x;
    if (i >= BATCH * 2) return;
    int b = i >> 1, o = i & 1;
    float s = bo[o];
    const float* fp = f2 + (size_t)b * 128;
#pragma unroll 8
    for (int k = 0; k < 128; k++) s += fp[k] * Wo[k * 2 + o];
    out[i] = s;
}

// ---------------- host ----------------
static inline int cdiv(int a, int b) { return (a + b - 1) / b; }
static inline dim3 ggrid(int M, int N) { return dim3(cdiv(N, 64), cdiv(M, 128), 1); }

extern "C" void kernel_launch(void* const* d_in, const int* in_sizes, int n_in,
                              void* d_out, int out_size)
{
    const float* x1   = (const float*)d_in[0];
    const int*   ei1  = (const int*)  d_in[1];
    const float* x2   = (const float*)d_in[3];
    const int*   ei2  = (const int*)  d_in[4];
    const float* cell = (const float*)d_in[6];
    const float *Wc1 = (const float*)d_in[7],  *bc1 = (const float*)d_in[8];
    const float *Wc2 = (const float*)d_in[9],  *bc2 = (const float*)d_in[10];
    const float *Wc3 = (const float*)d_in[11], *bc3 = (const float*)d_in[12];
    const float *Wg1 = (const float*)d_in[13], *bg1 = (const float*)d_in[14];
    const float *Wg2 = (const float*)d_in[15], *bg2 = (const float*)d_in[16];
    const float *Wr1 = (const float*)d_in[17], *br1 = (const float*)d_in[18];
    const float *Wr2 = (const float*)d_in[19], *br2 = (const float*)d_in[20];
    const float *Wr3 = (const float*)d_in[21], *br3 = (const float*)d_in[22];
    const float *Wf1 = (const float*)d_in[23], *bf1 = (const float*)d_in[24];
    const float *Wf2 = (const float*)d_in[25], *bf2 = (const float*)d_in[26];
    const float *Wo  = (const float*)d_in[27], *bo  = (const float*)d_in[28];

    const int* s1 = ei1;  const int* d1 = ei1 + N_EDGES;
    const int* s2 = ei2;  const int* d2 = ei2 + N_EDGES;

    float *H_, *A_, *B_, *dinv_, *pool_, *p1_, *gt_, *acc_, *cv1_, *cv2_, *xc_, *f1_, *f2_, *rn_;
    int *cnt_, *rowptr_, *cursor_, *csrc_;
    cudaGetSymbolAddress((void**)&H_,     g_H);
    cudaGetSymbolAddress((void**)&A_,     g_A);
    cudaGetSymbolAddress((void**)&B_,     g_B2);
    cudaGetSymbolAddress((void**)&dinv_,  g_dinv);
    cudaGetSymbolAddress((void**)&cnt_,   g_cnt);
    cudaGetSymbolAddress((void**)&rowptr_,g_rowptr);
    cudaGetSymbolAddress((void**)&cursor_,g_cursor);
    cudaGetSymbolAddress((void**)&csrc_,  g_csrc);
    cudaGetSymbolAddress((void**)&pool_,  g_pool);
    cudaGetSymbolAddress((void**)&p1_,    g_p1);
    cudaGetSymbolAddress((void**)&gt_,    g_gt);
    cudaGetSymbolAddress((void**)&acc_,   g_acc);
    cudaGetSymbolAddress((void**)&cv1_,   g_cv1);
    cudaGetSymbolAddress((void**)&cv2_,   g_cv2);
    cudaGetSymbolAddress((void**)&xc_,    g_xc);
    cudaGetSymbolAddress((void**)&f1_,    g_f1);
    cudaGetSymbolAddress((void**)&f2_,    g_f2);
    cudaGetSymbolAddress((void**)&rn_,    g_rn);

    // ---- cell branch ----
    k_rnorm<<<BATCH, 256>>>(cell, rn_);
    cudaMemsetAsync(acc_, 0, (size_t)BATCH * 512 * sizeof(float));
    {
        int kChunk = cdiv(cdiv(37261, SPLITK), BK) * BK;
        gemm_h2<true><<<dim3(8, 8, SPLITK), 256>>>(cell, 37261, Wr1, 512, acc_, 512,
                                                   BATCH, 512, 37261, kChunk,
                                                   nullptr, nullptr, 0);
    }
    k_cellepi<<<cdiv(BATCH * 512, 256), 256>>>(cv1_, acc_, rn_, br1);
    gemm_h2<false><<<ggrid(BATCH, 256), 256>>>(cv1_, 512, Wr2, 256, cv2_, 256,
                                               BATCH, 256, 512, 512, br2, nullptr, 1);
    gemm_h2<false><<<ggrid(BATCH, 128), 256>>>(cv2_, 256, Wr3, 128, xc_ + 256, 384,
                                               BATCH, 128, 256, 256, br3, nullptr, 0);

    // ---- CSR build (both branches stacked) ----
    cudaMemsetAsync(cnt_, 0, N_STACK * sizeof(int));
    k_hist  <<<cdiv(E2, 256), 256>>>(cnt_, d1, d2);
    k_dinv  <<<cdiv(N_STACK, 256), 256>>>(dinv_, cnt_);
    k_scan  <<<1, 1024>>>(cnt_, rowptr_, cursor_);
    k_bucket<<<cdiv(E2, 256), 256>>>(cursor_, csrc_, s1, d1, s2, d2);

    // ---- conv1: agg(x) -> GEMM(78->78) + bias + relu ----
    k_gather<2><<<cdiv(N_STACK * 39, 256), 256>>>(A_, 78, x1, x2, 78, 39,
                                                  rowptr_, csrc_, dinv_);
    gemm_h2<false><<<ggrid(N_STACK, 78), 256>>>(A_, 78, Wc1, 78, H_, 78,
                                                N_STACK, 78, 78, 78, bc1, nullptr, 1);

    // ---- conv2: agg(C1) -> GEMM(78->156) + bias + relu ----
    k_gather<2><<<cdiv(N_STACK * 39, 256), 256>>>(A_, 78, H_, H_ + (size_t)N_NODES * 78,
                                                  78, 39, rowptr_, csrc_, dinv_);
    gemm_h2<false><<<ggrid(N_STACK, 156), 256>>>(A_, 78, Wc2, 156, B_, 156,
                                                 N_STACK, 156, 78, 78, bc2, nullptr, 1);

    // ---- conv3: agg(C2) -> GEMM(156->312) + bias + relu ----
    k_gather<4><<<cdiv(N_STACK * 39, 256), 256>>>(A_, 156, B_, B_ + (size_t)N_NODES * 156,
                                                  156, 39, rowptr_, csrc_, dinv_);
    gemm_h2<false><<<ggrid(N_STACK, 312), 256>>>(A_, 156, Wc3, 312, H_, 312,
                                                 N_STACK, 312, 156, 156, bc3, nullptr, 1);

    // ---- pool + shared MLP head (M = 2048) ----
    k_pool<<<cdiv(2 * BATCH * 312, 256), 256>>>(pool_, H_);
    gemm_h2<false><<<ggrid(2 * BATCH, 156), 256>>>(pool_, 312, Wg1, 156, p1_, 156,
                                                   2 * BATCH, 156, 312, 312, bg1, nullptr, 1);
    gemm_h2<false><<<ggrid(2 * BATCH, 128), 256>>>(p1_, 156, Wg2, 128, gt_, 128,
                                                   2 * BATCH, 128, 156, 156, bg2, nullptr, 0);
    k_xcpack<<<cdiv(BATCH * 256, 256), 256>>>(xc_, gt_);

    // ---- fusion head ----
    gemm_h2<false><<<ggrid(BATCH, 512), 256>>>(xc_, 384, Wf1, 512, f1_, 512,
                                               BATCH, 512, 384, 384, bf1, nullptr, 1);
    gemm_h2<false><<<ggrid(BATCH, 128), 256>>>(f1_, 512, Wf2, 128, f2_, 128,
                                               BATCH, 128, 512, 512, bf2, nullptr, 1);
    k_out<<<cdiv(BATCH * 2, 256), 256>>>(f2_, Wo, bo, (float*)d_out);
}

// round 5
// speedup vs baseline: 6.4727x; 1.4102x over previous
#include <cuda_runtime.h>
#include <cuda_fp16.h>
#include <cstdint>
#include <cstddef>

#define N_NODES 40960
#define N_STACK 81920
#define N_EDGES 131072
#define E2      262144
#define BATCH   1024
#define NPG     40
#define PADK    40
#define KCELL   37376      // 37261 padded to x32
#define SPLITK  8

// ---------------- fp32 scratch ----------------
__device__ float g_H  [N_STACK * 312];
__device__ float g_B2 [N_STACK * 156];
__device__ float g_acc[BATCH * 512];
__device__ float g_gt [2 * BATCH * 128];
__device__ float g_f2 [BATCH * 128];
__device__ float g_rn [BATCH];
__device__ float g_dinv[N_STACK];
__device__ int   g_cnt[N_STACK];
__device__ int   g_rowptr[N_STACK + 1];
__device__ int   g_cursor[N_STACK];
__device__ int   g_csrc[E2];

// ---------------- fp16 hi/lo planes (pads never written -> stay 0) ----------------
__device__ __align__(16) __half g_cellh[BATCH * KCELL];
__device__ __align__(16) __half g_celll[BATCH * KCELL];
__device__ __align__(16) __half g_wr1th[512 * KCELL];
__device__ __align__(16) __half g_wr1tl[512 * KCELL];

__device__ __align__(16) __half g_A1h[N_STACK * 96],  g_A1l[N_STACK * 96];
__device__ __align__(16) __half g_A2h[N_STACK * 96],  g_A2l[N_STACK * 96];
__device__ __align__(16) __half g_A3h[N_STACK * 160], g_A3l[N_STACK * 160];

__device__ __align__(16) __half g_wc1th[128 * 96],   g_wc1tl[128 * 96];
__device__ __align__(16) __half g_wc2th[256 * 96],   g_wc2tl[256 * 96];
__device__ __align__(16) __half g_wc3th[384 * 160],  g_wc3tl[384 * 160];
__device__ __align__(16) __half g_wg1th[256 * 320],  g_wg1tl[256 * 320];
__device__ __align__(16) __half g_wg2th[128 * 160],  g_wg2tl[128 * 160];
__device__ __align__(16) __half g_wr2th[256 * 512],  g_wr2tl[256 * 512];
__device__ __align__(16) __half g_wr3th[128 * 256],  g_wr3tl[128 * 256];
__device__ __align__(16) __half g_wf1th[512 * 384],  g_wf1tl[512 * 384];
__device__ __align__(16) __half g_wf2th[128 * 512],  g_wf2tl[128 * 512];

__device__ __align__(16) __half g_poolh[2 * BATCH * 320], g_pooll[2 * BATCH * 320];
__device__ __align__(16) __half g_p1h [2 * BATCH * 160],  g_p1l [2 * BATCH * 160];
__device__ __align__(16) __half g_cv1h[BATCH * 512], g_cv1l[BATCH * 512];
__device__ __align__(16) __half g_cv2h[BATCH * 256], g_cv2l[BATCH * 256];
__device__ __align__(16) __half g_xch [BATCH * 384], g_xcl [BATCH * 384];
__device__ __align__(16) __half g_f1h [BATCH * 512], g_f1l [BATCH * 512];

// ---------------- helpers ----------------
__device__ __forceinline__ void cp16(void* dst, const void* src) {
    unsigned d = (unsigned)__cvta_generic_to_shared(dst);
    asm volatile("cp.async.cg.shared.global [%0], [%1], 16;\n" :: "r"(d), "l"(src));
}
__device__ __forceinline__ void hsplit(float v, __half& h, __half& l) {
    h = __float2half_rn(v);
    l = __float2half_rn(v - __half2float(h));
}

#define MMA16(d, a, b)                                                           \
    asm volatile(                                                                \
        "mma.sync.aligned.m16n8k16.row.col.f32.f16.f16.f32 "                     \
        "{%0,%1,%2,%3},{%4,%5,%6,%7},{%8,%9},{%0,%1,%2,%3};"                     \
        : "+f"((d)[0]), "+f"((d)[1]), "+f"((d)[2]), "+f"((d)[3])                 \
        : "r"((a)[0]), "r"((a)[1]), "r"((a)[2]), "r"((a)[3]),                    \
          "r"((b)[0]), "r"((b)[1]))

// ---------------- GEMM: pre-split fp16 hi/lo, cp.async double-buffer ----------------
// C[M,N] = A[M,K] @ Bt[N,K]^T. Tile 128x128x32, 8 warps (2m x 4n), warp 64x32.
// 3-pass (ah*bh + ah*bl + al*bh) ~= fp32 accuracy. All loads unguarded (padded bufs).
__global__ void __launch_bounds__(256, 2) gemm_hs(
    const __half* __restrict__ Ah, const __half* __restrict__ Al, int lda,
    const __half* __restrict__ Bh, const __half* __restrict__ Bl, int ldb,
    float* C, int ldc, __half* Ch, __half* Cl, int ldch,
    int M, int N, int kTot, int kChunk,
    const float* __restrict__ bias, int relu, int atomic)
{
    extern __shared__ __align__(16) __half smem[];
    __half* AsH = smem;
    __half* AsL = AsH + 2 * 128 * PADK;
    __half* BsH = AsL + 2 * 128 * PADK;
    __half* BsL = BsH + 2 * 128 * PADK;

    const int tid  = threadIdx.x;
    const int lane = tid & 31;
    const int wid  = tid >> 5;
    const int wm   = wid >> 2;        // 2 warp rows (64 each)
    const int wn   = wid & 3;         // 4 warp cols (32 each)
    const int g    = lane >> 2;
    const int tg2  = (lane & 3) * 2;
    const int rowBase = blockIdx.y * 128;
    const int colBase = blockIdx.x * 128;
    const int kStart  = blockIdx.z * kChunk;
    const int kEnd    = min(kTot, kStart + kChunk);
    const int T       = (kEnd - kStart) >> 5;

    float acc[4][4][4] = {};

    auto stage_load = [&](int s, int k0) {
        __half* aH = AsH + s * 128 * PADK;
        __half* aL = AsL + s * 128 * PADK;
        __half* bH = BsH + s * 128 * PADK;
        __half* bL = BsL + s * 128 * PADK;
#pragma unroll
        for (int i = 0; i < 2; i++) {
            int c = tid + i * 256;
            int r = c >> 2, cc = (c & 3) * 8;
            size_t ga = (size_t)(rowBase + r) * lda + k0 + cc;
            size_t gb = (size_t)(colBase + r) * ldb + k0 + cc;
            int so = r * PADK + cc;
            cp16(aH + so, Ah + ga);
            cp16(aL + so, Al + ga);
            cp16(bH + so, Bh + gb);
            cp16(bL + so, Bl + gb);
        }
        asm volatile("cp.async.commit_group;\n");
    };

    stage_load(0, kStart);

    for (int t = 0; t < T; t++) {
        asm volatile("cp.async.wait_group 0;\n");
        __syncthreads();
        if (t + 1 < T) stage_load((t + 1) & 1, kStart + ((t + 1) << 5));

        const __half* cAh = AsH + (t & 1) * 128 * PADK;
        const __half* cAl = AsL + (t & 1) * 128 * PADK;
        const __half* cBh = BsH + (t & 1) * 128 * PADK;
        const __half* cBl = BsL + (t & 1) * 128 * PADK;

#pragma unroll
        for (int ks = 0; ks < 2; ks++) {
            const int kb = ks * 16;
            unsigned bh[4][2], bl[4][2];
#pragma unroll
            for (int nt = 0; nt < 4; nt++) {
                int c0 = wn * 32 + nt * 8 + g;
                const __half* pb = cBh + c0 * PADK + kb + tg2;
                const __half* pl = cBl + c0 * PADK + kb + tg2;
                bh[nt][0] = *(const unsigned*)pb;
                bh[nt][1] = *(const unsigned*)(pb + 8);
                bl[nt][0] = *(const unsigned*)pl;
                bl[nt][1] = *(const unsigned*)(pl + 8);
            }
#pragma unroll
            for (int mt = 0; mt < 4; mt++) {
                int r0 = wm * 64 + mt * 16 + g;
                const __half* pa = cAh + r0 * PADK + kb + tg2;
                const __half* qa = cAl + r0 * PADK + kb + tg2;
                unsigned ah[4], al[4];
                ah[0] = *(const unsigned*)pa;
                ah[1] = *(const unsigned*)(pa + 8 * PADK);
                ah[2] = *(const unsigned*)(pa + 8);
                ah[3] = *(const unsigned*)(pa + 8 * PADK + 8);
                al[0] = *(const unsigned*)qa;
                al[1] = *(const unsigned*)(qa + 8 * PADK);
                al[2] = *(const unsigned*)(qa + 8);
                al[3] = *(const unsigned*)(qa + 8 * PADK + 8);
#pragma unroll
                for (int nt = 0; nt < 4; nt++) {
                    MMA16(acc[mt][nt], ah, bh[nt]);
                    MMA16(acc[mt][nt], ah, bl[nt]);
                    MMA16(acc[mt][nt], al, bh[nt]);
                }
            }
        }
        __syncthreads();
    }

#pragma unroll
    for (int mt = 0; mt < 4; mt++)
#pragma unroll
        for (int nt = 0; nt < 4; nt++) {
            int r0 = rowBase + wm * 64 + mt * 16 + g;
            int cb = colBase + wn * 32 + nt * 8 + tg2;
            if (cb >= N) continue;           // N even -> cb+1 < N too
            float* a = acc[mt][nt];
            if (atomic) {
                atomicAdd(&C[(size_t)r0 * ldc + cb],           a[0]);
                atomicAdd(&C[(size_t)r0 * ldc + cb + 1],       a[1]);
                atomicAdd(&C[(size_t)(r0 + 8) * ldc + cb],     a[2]);
                atomicAdd(&C[(size_t)(r0 + 8) * ldc + cb + 1], a[3]);
            } else {
                float b0 = bias ? bias[cb] : 0.f;
                float b1 = bias ? bias[cb + 1] : 0.f;
                float v0 = a[0] + b0, v1 = a[1] + b1, v2 = a[2] + b0, v3 = a[3] + b1;
                if (relu) {
                    v0 = fmaxf(v0, 0.f); v1 = fmaxf(v1, 0.f);
                    v2 = fmaxf(v2, 0.f); v3 = fmaxf(v3, 0.f);
                }
                if (C) {
                    C[(size_t)r0 * ldc + cb] = v0;
                    C[(size_t)r0 * ldc + cb + 1] = v1;
                    C[(size_t)(r0 + 8) * ldc + cb] = v2;
                    C[(size_t)(r0 + 8) * ldc + cb + 1] = v3;
                }
                if (Ch) {
                    __half h, l;
                    __half2 hh, ll;
                    hsplit(v0, h, l); hh.x = h; ll.x = l;
                    hsplit(v1, h, l); hh.y = h; ll.y = l;
                    *(__half2*)(Ch + (size_t)r0 * ldch + cb) = hh;
                    *(__half2*)(Cl + (size_t)r0 * ldch + cb) = ll;
                    hsplit(v2, h, l); hh.x = h; ll.x = l;
                    hsplit(v3, h, l); hh.y = h; ll.y = l;
                    *(__half2*)(Ch + (size_t)(r0 + 8) * ldch + cb) = hh;
                    *(__half2*)(Cl + (size_t)(r0 + 8) * ldch + cb) = ll;
                }
            }
        }
}

// ---------------- split kernels ----------------
// cell: fused rownorm + split (one read of the 152MB matrix)
__global__ void k_cellprep(const float* __restrict__ cell,
                           __half* __restrict__ ch, __half* __restrict__ cl,
                           float* __restrict__ rn)
{
    __shared__ float sm[256];
    int b = blockIdx.x;
    const float* row = cell + (size_t)b * 37261;
    __half* oh = ch + (size_t)b * KCELL;
    __half* ol = cl + (size_t)b * KCELL;
    float s = 0.f;
    for (int i = threadIdx.x; i < 37261; i += 256) {
        float v = row[i];
        s += v * v;
        __half h, l; hsplit(v, h, l);
        oh[i] = h; ol[i] = l;
    }
    sm[threadIdx.x] = s;
    __syncthreads();
    for (int off = 128; off > 0; off >>= 1) {
        if (threadIdx.x < off) sm[threadIdx.x] += sm[threadIdx.x + off];
        __syncthreads();
    }
    if (threadIdx.x == 0) rn[b] = 1.f / fmaxf(sqrtf(sm[0]), 1e-12f);
}

// weight transpose-split: src [K][N] fp32 -> dst [N][ldk] hi/lo
__global__ void k_wsplit(const float* __restrict__ src, int K, int N,
                         __half* __restrict__ dh, __half* __restrict__ dl, int ldk)
{
    __shared__ float t[32][33];
    int n0 = blockIdx.x * 32, k0 = blockIdx.y * 32;
#pragma unroll
    for (int j = 0; j < 4; j++) {
        int k = k0 + threadIdx.y + j * 8;
        int n = n0 + threadIdx.x;
        t[threadIdx.y + j * 8][threadIdx.x] =
            (k < K && n < N) ? src[(size_t)k * N + n] : 0.f;
    }
    __syncthreads();
#pragma unroll
    for (int j = 0; j < 4; j++) {
        int n = n0 + threadIdx.y + j * 8;
        int k = k0 + threadIdx.x;
        if (n < N && k < K) {
            float v = t[threadIdx.x][threadIdx.y + j * 8];
            __half h, l; hsplit(v, h, l);
            dh[(size_t)n * ldk + k] = h;
            dl[(size_t)n * ldk + k] = l;
        }
    }
}

// ---------------- CSR build ----------------
__global__ void k_hist(int* __restrict__ cnt, const int* __restrict__ d1,
                       const int* __restrict__ d2) {
    int e = blockIdx.x * blockDim.x + threadIdx.x;
    if (e >= E2) return;
    int d = (e < N_EDGES) ? d1[e] : (d2[e - N_EDGES] + N_NODES);
    atomicAdd(&cnt[d], 1);
}
__global__ void k_dinv(float* __restrict__ dinv, const int* __restrict__ cnt) {
    int i = blockIdx.x * blockDim.x + threadIdx.x;
    if (i < N_STACK) dinv[i] = rsqrtf((float)cnt[i] + 1.f);
}
__global__ void __launch_bounds__(1024) k_scan(const int* __restrict__ cnt,
                                               int* __restrict__ rowptr,
                                               int* __restrict__ cursor) {
    __shared__ int sm[1024];
    const int CH = N_STACK / 1024;
    int t = threadIdx.x;
    int base = t * CH;
    int s = 0;
#pragma unroll 4
    for (int j = 0; j < CH; j++) s += cnt[base + j];
    sm[t] = s;
    __syncthreads();
    for (int off = 1; off < 1024; off <<= 1) {
        int v = (t >= off) ? sm[t - off] : 0;
        __syncthreads();
        sm[t] += v;
        __syncthreads();
    }
    int run = (t > 0) ? sm[t - 1] : 0;
    for (int j = 0; j < CH; j++) {
        rowptr[base + j] = run;
        cursor[base + j] = run;
        run += cnt[base + j];
    }
    if (t == 1023) rowptr[N_STACK] = run;
}
__global__ void k_bucket(int* __restrict__ cursor, int* __restrict__ csrc,
                         const int* __restrict__ s1, const int* __restrict__ d1,
                         const int* __restrict__ s2, const int* __restrict__ d2) {
    int e = blockIdx.x * blockDim.x + threadIdx.x;
    if (e >= E2) return;
    int s, d;
    if (e < N_EDGES) { s = s1[e]; d = d1[e]; }
    else             { s = s2[e - N_EDGES] + N_NODES; d = d2[e - N_EDGES] + N_NODES; }
    int pos = atomicAdd(&cursor[d], 1);
    csrc[pos] = s;
}

// ---------------- gather: fp32 in -> fp16 hi/lo planes out ----------------
template <int VEC>
__global__ void k_gatherH(__half* __restrict__ oh, __half* __restrict__ ol, int ldo,
                          const float* __restrict__ X1, const float* __restrict__ X2,
                          int ldin, int fvec,
                          const int* __restrict__ rowptr, const int* __restrict__ csrc,
                          const float* __restrict__ dinv)
{
    long long i = (long long)blockIdx.x * blockDim.x + threadIdx.x;
    if (i >= (long long)N_STACK * fvec) return;
    int n = (int)(i / fvec);
    int f = (int)(i - (long long)n * fvec) * VEC;

    const float* Xn = (n < N_NODES) ? X1 + (size_t)n * ldin
                                    : X2 + (size_t)(n - N_NODES) * ldin;
    float dn = dinv[n];
    int b0 = rowptr[n], b1 = rowptr[n + 1];

    float r[VEC];
#pragma unroll
    for (int q = 0; q < VEC; q++) r[q] = Xn[f + q] * dn;
    for (int j = b0; j < b1; j++) {
        int s = csrc[j];
        const float* Xs = (s < N_NODES) ? X1 + (size_t)s * ldin
                                        : X2 + (size_t)(s - N_NODES) * ldin;
        float ds = dinv[s];
        if (VEC == 4) {
            float4 u = *reinterpret_cast<const float4*>(Xs + f);
            r[0] += u.x * ds; r[1] += u.y * ds; r[2] += u.z * ds; r[3] += u.w * ds;
        } else {
            float2 u = *reinterpret_cast<const float2*>(Xs + f);
            r[0] += u.x * ds; r[1] += u.y * ds;
        }
    }
    __half* ph = oh + (size_t)n * ldo + f;
    __half* pl = ol + (size_t)n * ldo + f;
#pragma unroll
    for (int q = 0; q < VEC; q += 2) {
        __half h, l; __half2 hh, ll;
        hsplit(r[q] * dn, h, l);     hh.x = h; ll.x = l;
        hsplit(r[q + 1] * dn, h, l); hh.y = h; ll.y = l;
        *(__half2*)(ph + q) = hh;
        *(__half2*)(pl + q) = ll;
    }
}

// ---------------- misc ----------------
__global__ void k_pool(__half* __restrict__ ph, __half* __restrict__ pl,
                       const float* __restrict__ X) {
    int i = blockIdx.x * blockDim.x + threadIdx.x;
    if (i >= 2 * BATCH * 312) return;
    int gg = i / 312, f = i - gg * 312;
    const float* p = X + (size_t)gg * NPG * 312 + f;
    float m = p[0];
#pragma unroll 8
    for (int j = 1; j < NPG; j++) m = fmaxf(m, p[(size_t)j * 312]);
    __half h, l; hsplit(m, h, l);
    ph[(size_t)gg * 320 + f] = h;
    pl[(size_t)gg * 320 + f] = l;
}

__global__ void k_cellepi(__half* __restrict__ oh, __half* __restrict__ ol,
                          const float* __restrict__ acc,
                          const float* __restrict__ rn, const float* __restrict__ bias)
{
    int i = blockIdx.x * blockDim.x + threadIdx.x;
    if (i >= BATCH * 512) return;
    int r = i >> 9, c = i & 511;
    float v = fmaxf(acc[i] * rn[r] + bias[c], 0.f);
    __half h, l; hsplit(v, h, l);
    oh[i] = h; ol[i] = l;
}

__global__ void k_xcpack(__half* __restrict__ xh, __half* __restrict__ xl,
                         const float* __restrict__ gt) {
    int i = blockIdx.x * blockDim.x + threadIdx.x;
    if (i >= BATCH * 256) return;
    int b = i >> 8, c = i & 255;
    float v = (c < 128) ? gt[(size_t)b * 128 + c]
                        : gt[(size_t)(BATCH + b) * 128 + (c - 128)];
    __half h, l; hsplit(v, h, l);
    xh[(size_t)b * 384 + c] = h;
    xl[(size_t)b * 384 + c] = l;
}

__global__ void k_out(const float* __restrict__ f2, const float* __restrict__ Wo,
                      const float* __restrict__ bo, float* __restrict__ out) {
    int i = blockIdx.x * blockDim.x + threadIdx.x;
    if (i >= BATCH * 2) return;
    int b = i >> 1, o = i & 1;
    float s = bo[o];
    const float* fp = f2 + (size_t)b * 128;
#pragma unroll 8
    for (int k = 0; k < 128; k++) s += fp[k] * Wo[k * 2 + o];
    out[i] = s;
}

// ---------------- host ----------------
static inline int cdiv(int a, int b) { return (a + b - 1) / b; }
#define SMEM_GEMM (8 * 128 * PADK * (int)sizeof(__half))   // 81920 B

#define SYM(p, s) cudaGetSymbolAddress((void**)&(p), s)

extern "C" void kernel_launch(void* const* d_in, const int* in_sizes, int n_in,
                              void* d_out, int out_size)
{
    const float* x1   = (const float*)d_in[0];
    const int*   ei1  = (const int*)  d_in[1];
    const float* x2   = (const float*)d_in[3];
    const int*   ei2  = (const int*)  d_in[4];
    const float* cell = (const float*)d_in[6];
    const float *Wc1 = (const float*)d_in[7],  *bc1 = (const float*)d_in[8];
    const float *Wc2 = (const float*)d_in[9],  *bc2 = (const float*)d_in[10];
    const float *Wc3 = (const float*)d_in[11], *bc3 = (const float*)d_in[12];
    const float *Wg1 = (const float*)d_in[13], *bg1 = (const float*)d_in[14];
    const float *Wg2 = (const float*)d_in[15], *bg2 = (const float*)d_in[16];
    const float *Wr1 = (const float*)d_in[17], *br1 = (const float*)d_in[18];
    const float *Wr2 = (const float*)d_in[19], *br2 = (const float*)d_in[20];
    const float *Wr3 = (const float*)d_in[21], *br3 = (const float*)d_in[22];
    const float *Wf1 = (const float*)d_in[23], *bf1 = (const float*)d_in[24];
    const float *Wf2 = (const float*)d_in[25], *bf2 = (const float*)d_in[26];
    const float *Wo  = (const float*)d_in[27], *bo  = (const float*)d_in[28];

    const int* s1 = ei1;  const int* d1 = ei1 + N_EDGES;
    const int* s2 = ei2;  const int* d2 = ei2 + N_EDGES;

    static int attr_done = 0;
    cudaFuncSetAttribute(gemm_hs, cudaFuncAttributeMaxDynamicSharedMemorySize, SMEM_GEMM);
    (void)attr_done;

    float *H_, *B_, *acc_, *gt_, *f2_, *rn_, *dinv_;
    int *cnt_, *rowptr_, *cursor_, *csrc_;
    __half *cellh, *celll, *wr1th, *wr1tl;
    __half *A1h, *A1l, *A2h, *A2l, *A3h, *A3l;
    __half *wc1th, *wc1tl, *wc2th, *wc2tl, *wc3th, *wc3tl;
    __half *wg1th, *wg1tl, *wg2th, *wg2tl;
    __half *wr2th, *wr2tl, *wr3th, *wr3tl, *wf1th, *wf1tl, *wf2th, *wf2tl;
    __half *poolh, *pooll, *p1h, *p1l, *cv1h, *cv1l, *cv2h, *cv2l;
    __half *xch, *xcl, *f1h, *f1l;

    SYM(H_, g_H); SYM(B_, g_B2); SYM(acc_, g_acc); SYM(gt_, g_gt);
    SYM(f2_, g_f2); SYM(rn_, g_rn); SYM(dinv_, g_dinv);
    SYM(cnt_, g_cnt); SYM(rowptr_, g_rowptr); SYM(cursor_, g_cursor); SYM(csrc_, g_csrc);
    SYM(cellh, g_cellh); SYM(celll, g_celll); SYM(wr1th, g_wr1th); SYM(wr1tl, g_wr1tl);
    SYM(A1h, g_A1h); SYM(A1l, g_A1l); SYM(A2h, g_A2h); SYM(A2l, g_A2l);
    SYM(A3h, g_A3h); SYM(A3l, g_A3l);
    SYM(wc1th, g_wc1th); SYM(wc1tl, g_wc1tl); SYM(wc2th, g_wc2th); SYM(wc2tl, g_wc2tl);
    SYM(wc3th, g_wc3th); SYM(wc3tl, g_wc3tl);
    SYM(wg1th, g_wg1th); SYM(wg1tl, g_wg1tl); SYM(wg2th, g_wg2th); SYM(wg2tl, g_wg2tl);
    SYM(wr2th, g_wr2th); SYM(wr2tl, g_wr2tl); SYM(wr3th, g_wr3th); SYM(wr3tl, g_wr3tl);
    SYM(wf1th, g_wf1th); SYM(wf1tl, g_wf1tl); SYM(wf2th, g_wf2th); SYM(wf2tl, g_wf2tl);
    SYM(poolh, g_poolh); SYM(pooll, g_pooll); SYM(p1h, g_p1h); SYM(p1l, g_p1l);
    SYM(cv1h, g_cv1h); SYM(cv1l, g_cv1l); SYM(cv2h, g_cv2h); SYM(cv2l, g_cv2l);
    SYM(xch, g_xch); SYM(xcl, g_xcl); SYM(f1h, g_f1h); SYM(f1l, g_f1l);

    dim3 blk32(32, 8);

    // ---- splits / prep ----
    k_cellprep<<<BATCH, 256>>>(cell, cellh, celll, rn_);
    k_wsplit<<<dim3(16, 1165), blk32>>>(Wr1, 37261, 512, wr1th, wr1tl, KCELL);
    k_wsplit<<<dim3(3, 3),   blk32>>>(Wc1, 78, 78,   wc1th, wc1tl, 96);
    k_wsplit<<<dim3(5, 3),   blk32>>>(Wc2, 78, 156,  wc2th, wc2tl, 96);
    k_wsplit<<<dim3(10, 5),  blk32>>>(Wc3, 156, 312, wc3th, wc3tl, 160);
    k_wsplit<<<dim3(5, 10),  blk32>>>(Wg1, 312, 156, wg1th, wg1tl, 320);
    k_wsplit<<<dim3(4, 5),   blk32>>>(Wg2, 156, 128, wg2th, wg2tl, 160);
    k_wsplit<<<dim3(8, 16),  blk32>>>(Wr2, 512, 256, wr2th, wr2tl, 512);
    k_wsplit<<<dim3(4, 8),   blk32>>>(Wr3, 256, 128, wr3th, wr3tl, 256);
    k_wsplit<<<dim3(16, 12), blk32>>>(Wf1, 384, 512, wf1th, wf1tl, 384);
    k_wsplit<<<dim3(4, 16),  blk32>>>(Wf2, 512, 128, wf2th, wf2tl, 512);

    // ---- cell branch ----
    cudaMemsetAsync(acc_, 0, (size_t)BATCH * 512 * sizeof(float));
    gemm_hs<<<dim3(4, 8, SPLITK), 256, SMEM_GEMM>>>(
        cellh, celll, KCELL, wr1th, wr1tl, KCELL,
        acc_, 512, nullptr, nullptr, 0,
        BATCH, 512, KCELL, KCELL / SPLITK, nullptr, 0, 1);
    k_cellepi<<<cdiv(BATCH * 512, 256), 256>>>(cv1h, cv1l, acc_, rn_, br1);
    gemm_hs<<<dim3(2, 8, 1), 256, SMEM_GEMM>>>(
        cv1h, cv1l, 512, wr2th, wr2tl, 512,
        nullptr, 0, cv2h, cv2l, 256,
        BATCH, 256, 512, 512, br2, 1, 0);
    gemm_hs<<<dim3(1, 8, 1), 256, SMEM_GEMM>>>(
        cv2h, cv2l, 256, wr3th, wr3tl, 256,
        nullptr, 0, xch + 256, xcl + 256, 384,
        BATCH, 128, 256, 256, br3, 0, 0);

    // ---- CSR build ----
    cudaMemsetAsync(cnt_, 0, N_STACK * sizeof(int));
    k_hist  <<<cdiv(E2, 256), 256>>>(cnt_, d1, d2);
    k_dinv  <<<cdiv(N_STACK, 256), 256>>>(dinv_, cnt_);
    k_scan  <<<1, 1024>>>(cnt_, rowptr_, cursor_);
    k_bucket<<<cdiv(E2, 256), 256>>>(cursor_, csrc_, s1, d1, s2, d2);

    // ---- conv1 ----
    k_gatherH<2><<<cdiv(N_STACK * 39, 256), 256>>>(A1h, A1l, 96, x1, x2, 78, 39,
                                                   rowptr_, csrc_, dinv_);
    gemm_hs<<<dim3(1, 640, 1), 256, SMEM_GEMM>>>(
        A1h, A1l, 96, wc1th, wc1tl, 96,
        H_, 78, nullptr, nullptr, 0,
        N_STACK, 78, 96, 96, bc1, 1, 0);

    // ---- conv2 ----
    k_gatherH<2><<<cdiv(N_STACK * 39, 256), 256>>>(A2h, A2l, 96, H_,
                                                   H_ + (size_t)N_NODES * 78, 78, 39,
                                                   rowptr_, csrc_, dinv_);
    gemm_hs<<<dim3(2, 640, 1), 256, SMEM_GEMM>>>(
        A2h, A2l, 96, wc2th, wc2tl, 96,
        B_, 156, nullptr, nullptr, 0,
        N_STACK, 156, 96, 96, bc2, 1, 0);

    // ---- conv3 ----
    k_gatherH<4><<<cdiv(N_STACK * 39, 256), 256>>>(A3h, A3l, 160, B_,
                                                   B_ + (size_t)N_NODES * 156, 156, 39,
                                                   rowptr_, csrc_, dinv_);
    gemm_hs<<<dim3(3, 640, 1), 256, SMEM_GEMM>>>(
        A3h, A3l, 160, wc3th, wc3tl, 160,
        H_, 312, nullptr, nullptr, 0,
        N_STACK, 312, 160, 160, bc3, 1, 0);

    // ---- pool + shared drug head (M = 2048) ----
    k_pool<<<cdiv(2 * BATCH * 312, 256), 256>>>(poolh, pooll, H_);
    gemm_hs<<<dim3(2, 16, 1), 256, SMEM_GEMM>>>(
        poolh, pooll, 320, wg1th, wg1tl, 320,
        nullptr, 0, p1h, p1l, 160,
        2 * BATCH, 156, 320, 320, bg1, 1, 0);
    gemm_hs<<<dim3(1, 16, 1), 256, SMEM_GEMM>>>(
        p1h, p1l, 160, wg2th, wg2tl, 160,
        gt_, 128, nullptr, nullptr, 0,
        2 * BATCH, 128, 160, 160, bg2, 0, 0);
    k_xcpack<<<cdiv(BATCH * 256, 256), 256>>>(xch, xcl, gt_);

    // ---- fusion head ----
    gemm_hs<<<dim3(4, 8, 1), 256, SMEM_GEMM>>>(
        xch, xcl, 384, wf1th, wf1tl, 384,
        nullptr, 0, f1h, f1l, 512,
        BATCH, 512, 384, 384, bf1, 1, 0);
    gemm_hs<<<dim3(1, 8, 1), 256, SMEM_GEMM>>>(
        f1h, f1l, 512, wf2th, wf2tl, 512,
        f2_, 128, nullptr, nullptr, 0,
        BATCH, 128, 512, 512, bf2, 1, 0);
    k_out<<<cdiv(BATCH * 2, 256), 256>>>(f2_, Wo, bo, (float*)d_out);
}

// round 6
// speedup vs baseline: 7.1683x; 1.1075x over previous
#include <cuda_runtime.h>
#include <cuda_fp16.h>
#include <cstdint>
#include <cstddef>

#define N_NODES 40960
#define N_STACK 81920
#define N_EDGES 131072
#define E2      262144
#define BATCH   1024
#define NPG     40
#define PADK    40
#define KCELL   37376      // 37261 padded to x32
#define SPLITK  8

// ---------------- fp32 scratch ----------------
__device__ float g_H  [N_STACK * 312];
__device__ float g_B2 [N_STACK * 156];
__device__ float g_acc[BATCH * 512];
__device__ float g_gt [2 * BATCH * 128];
__device__ float g_f2 [BATCH * 128];
__device__ float g_rn [BATCH];
__device__ float g_dinv[N_STACK];
__device__ int   g_cnt[N_STACK];
__device__ int   g_rowptr[N_STACK + 1];
__device__ int   g_cursor[N_STACK];
__device__ int   g_csrc[E2];

// ---------------- fp16 hi/lo planes (pads never written -> stay 0) ----------------
__device__ __align__(16) __half g_cellh[BATCH * KCELL];
__device__ __align__(16) __half g_wr1th[512 * KCELL];
__device__ __align__(16) __half g_wr1tl[512 * KCELL];

__device__ __align__(16) __half g_A1h[N_STACK * 96],  g_A1l[N_STACK * 96];
__device__ __align__(16) __half g_A2h[N_STACK * 96],  g_A2l[N_STACK * 96];
__device__ __align__(16) __half g_A3h[N_STACK * 160], g_A3l[N_STACK * 160];

__device__ __align__(16) __half g_wc1th[128 * 96],   g_wc1tl[128 * 96];
__device__ __align__(16) __half g_wc2th[256 * 96],   g_wc2tl[256 * 96];
__device__ __align__(16) __half g_wc3th[384 * 160],  g_wc3tl[384 * 160];
__device__ __align__(16) __half g_wg1th[256 * 320],  g_wg1tl[256 * 320];
__device__ __align__(16) __half g_wg2th[128 * 160],  g_wg2tl[128 * 160];
__device__ __align__(16) __half g_wr2th[256 * 512],  g_wr2tl[256 * 512];
__device__ __align__(16) __half g_wr3th[128 * 256],  g_wr3tl[128 * 256];
__device__ __align__(16) __half g_wf1th[512 * 384],  g_wf1tl[512 * 384];
__device__ __align__(16) __half g_wf2th[128 * 512],  g_wf2tl[128 * 512];

__device__ __align__(16) __half g_poolh[2 * BATCH * 320], g_pooll[2 * BATCH * 320];
__device__ __align__(16) __half g_p1h [2 * BATCH * 160],  g_p1l [2 * BATCH * 160];
__device__ __align__(16) __half g_cv1h[BATCH * 512], g_cv1l[BATCH * 512];
__device__ __align__(16) __half g_cv2h[BATCH * 256], g_cv2l[BATCH * 256];
__device__ __align__(16) __half g_xch [BATCH * 384], g_xcl [BATCH * 384];
__device__ __align__(16) __half g_f1h [BATCH * 512], g_f1l [BATCH * 512];

// ---------------- helpers ----------------
__device__ __forceinline__ void cp16(void* dst, const void* src) {
    unsigned d = (unsigned)__cvta_generic_to_shared(dst);
    asm volatile("cp.async.cg.shared.global [%0], [%1], 16;\n" :: "r"(d), "l"(src));
}
__device__ __forceinline__ void hsplit(float v, __half& h, __half& l) {
    h = __float2half_rn(v);
    l = __float2half_rn(v - __half2float(h));
}

#define MMA16(d, a, b)                                                           \
    asm volatile(                                                                \
        "mma.sync.aligned.m16n8k16.row.col.f32.f16.f16.f32 "                     \
        "{%0,%1,%2,%3},{%4,%5,%6,%7},{%8,%9},{%0,%1,%2,%3};"                     \
        : "+f"((d)[0]), "+f"((d)[1]), "+f"((d)[2]), "+f"((d)[3])                 \
        : "r"((a)[0]), "r"((a)[1]), "r"((a)[2]), "r"((a)[3]),                    \
          "r"((b)[0]), "r"((b)[1]))

// ---------------- GEMM: pre-split fp16 hi/lo, cp.async double-buffer ----------------
// C[M,N] = A[M,K] @ Bt[N,K]^T. Tile 128x128x32, 8 warps (2m x 4n), warp 64x32.
// ALO=true: 3-pass (ah*bh + ah*bl + al*bh). ALO=false: A hi-only, 2-pass.
template<bool ALO>
__global__ void __launch_bounds__(256, 2) gemm_hs(
    const __half* __restrict__ Ah, const __half* __restrict__ Al, int lda,
    const __half* __restrict__ Bh, const __half* __restrict__ Bl, int ldb,
    float* C, int ldc, __half* Ch, __half* Cl, int ldch,
    int M, int N, int kTot, int kChunk,
    const float* __restrict__ bias, int relu, int atomic)
{
    extern __shared__ __align__(16) __half smem[];
    const int PL = 2 * 128 * PADK;
    __half* AsH = smem;
    __half* AsL = ALO ? AsH + PL : nullptr;
    __half* BsH = AsH + (ALO ? 2 : 1) * PL;
    __half* BsL = BsH + PL;

    const int tid  = threadIdx.x;
    const int lane = tid & 31;
    const int wid  = tid >> 5;
    const int wm   = wid >> 2;
    const int wn   = wid & 3;
    const int g    = lane >> 2;
    const int tg2  = (lane & 3) * 2;
    const int rowBase = blockIdx.y * 128;
    const int colBase = blockIdx.x * 128;
    const int kStart  = blockIdx.z * kChunk;
    const int kEnd    = min(kTot, kStart + kChunk);
    const int T       = (kEnd - kStart) >> 5;

    float acc[4][4][4] = {};

    auto stage_load = [&](int s, int k0) {
        __half* aH = AsH + s * 128 * PADK;
        __half* bH = BsH + s * 128 * PADK;
        __half* bL = BsL + s * 128 * PADK;
#pragma unroll
        for (int i = 0; i < 2; i++) {
            int c = tid + i * 256;
            int r = c >> 2, cc = (c & 3) * 8;
            size_t ga = (size_t)(rowBase + r) * lda + k0 + cc;
            size_t gb = (size_t)(colBase + r) * ldb + k0 + cc;
            int so = r * PADK + cc;
            cp16(aH + so, Ah + ga);
            if (ALO) cp16(AsL + s * 128 * PADK + so, Al + ga);
            cp16(bH + so, Bh + gb);
            cp16(bL + so, Bl + gb);
        }
        asm volatile("cp.async.commit_group;\n");
    };

    stage_load(0, kStart);

    for (int t = 0; t < T; t++) {
        asm volatile("cp.async.wait_group 0;\n");
        __syncthreads();
        if (t + 1 < T) stage_load((t + 1) & 1, kStart + ((t + 1) << 5));

        const __half* cAh = AsH + (t & 1) * 128 * PADK;
        const __half* cAl = ALO ? AsL + (t & 1) * 128 * PADK : nullptr;
        const __half* cBh = BsH + (t & 1) * 128 * PADK;
        const __half* cBl = BsL + (t & 1) * 128 * PADK;

#pragma unroll
        for (int ks = 0; ks < 2; ks++) {
            const int kb = ks * 16;
            unsigned bh[4][2], bl[4][2];
#pragma unroll
            for (int nt = 0; nt < 4; nt++) {
                int c0 = wn * 32 + nt * 8 + g;
                const __half* pb = cBh + c0 * PADK + kb + tg2;
                const __half* pl = cBl + c0 * PADK + kb + tg2;
                bh[nt][0] = *(const unsigned*)pb;
                bh[nt][1] = *(const unsigned*)(pb + 8);
                bl[nt][0] = *(const unsigned*)pl;
                bl[nt][1] = *(const unsigned*)(pl + 8);
            }
#pragma unroll
            for (int mt = 0; mt < 4; mt++) {
                int r0 = wm * 64 + mt * 16 + g;
                const __half* pa = cAh + r0 * PADK + kb + tg2;
                unsigned ah[4], al[4];
                ah[0] = *(const unsigned*)pa;
                ah[1] = *(const unsigned*)(pa + 8 * PADK);
                ah[2] = *(const unsigned*)(pa + 8);
                ah[3] = *(const unsigned*)(pa + 8 * PADK + 8);
                if (ALO) {
                    const __half* qa = cAl + r0 * PADK + kb + tg2;
                    al[0] = *(const unsigned*)qa;
                    al[1] = *(const unsigned*)(qa + 8 * PADK);
                    al[2] = *(const unsigned*)(qa + 8);
                    al[3] = *(const unsigned*)(qa + 8 * PADK + 8);
                }
#pragma unroll
                for (int nt = 0; nt < 4; nt++) {
                    MMA16(acc[mt][nt], ah, bh[nt]);
                    MMA16(acc[mt][nt], ah, bl[nt]);
                    if (ALO) MMA16(acc[mt][nt], al, bh[nt]);
                }
            }
        }
        __syncthreads();
    }

#pragma unroll
    for (int mt = 0; mt < 4; mt++)
#pragma unroll
        for (int nt = 0; nt < 4; nt++) {
            int r0 = rowBase + wm * 64 + mt * 16 + g;
            int cb = colBase + wn * 32 + nt * 8 + tg2;
            if (cb >= N) continue;
            float* a = acc[mt][nt];
            if (atomic) {
                atomicAdd(&C[(size_t)r0 * ldc + cb],           a[0]);
                atomicAdd(&C[(size_t)r0 * ldc + cb + 1],       a[1]);
                atomicAdd(&C[(size_t)(r0 + 8) * ldc + cb],     a[2]);
                atomicAdd(&C[(size_t)(r0 + 8) * ldc + cb + 1], a[3]);
            } else {
                float b0 = bias ? bias[cb] : 0.f;
                float b1 = bias ? bias[cb + 1] : 0.f;
                float v0 = a[0] + b0, v1 = a[1] + b1, v2 = a[2] + b0, v3 = a[3] + b1;
                if (relu) {
                    v0 = fmaxf(v0, 0.f); v1 = fmaxf(v1, 0.f);
                    v2 = fmaxf(v2, 0.f); v3 = fmaxf(v3, 0.f);
                }
                if (C) {
                    C[(size_t)r0 * ldc + cb] = v0;
                    C[(size_t)r0 * ldc + cb + 1] = v1;
                    C[(size_t)(r0 + 8) * ldc + cb] = v2;
                    C[(size_t)(r0 + 8) * ldc + cb + 1] = v3;
                }
                if (Ch) {
                    __half h, l;
                    __half2 hh, ll;
                    hsplit(v0, h, l); hh.x = h; ll.x = l;
                    hsplit(v1, h, l); hh.y = h; ll.y = l;
                    *(__half2*)(Ch + (size_t)r0 * ldch + cb) = hh;
                    *(__half2*)(Cl + (size_t)r0 * ldch + cb) = ll;
                    hsplit(v2, h, l); hh.x = h; ll.x = l;
                    hsplit(v3, h, l); hh.y = h; ll.y = l;
                    *(__half2*)(Ch + (size_t)(r0 + 8) * ldch + cb) = hh;
                    *(__half2*)(Cl + (size_t)(r0 + 8) * ldch + cb) = ll;
                }
            }
        }
}

// ---------------- split kernels ----------------
// cell: fused rownorm + hi-only split (2-pass GEMM needs no lo plane)
__global__ void k_cellprep(const float* __restrict__ cell,
                           __half* __restrict__ ch, float* __restrict__ rn)
{
    __shared__ float sm[256];
    int b = blockIdx.x;
    const float* row = cell + (size_t)b * 37261;
    __half* oh = ch + (size_t)b * KCELL;
    float s = 0.f;
    for (int i = threadIdx.x; i < 37261; i += 256) {
        float v = row[i];
        s += v * v;
        oh[i] = __float2half_rn(v);
    }
    sm[threadIdx.x] = s;
    __syncthreads();
    for (int off = 128; off > 0; off >>= 1) {
        if (threadIdx.x < off) sm[threadIdx.x] += sm[threadIdx.x + off];
        __syncthreads();
    }
    if (threadIdx.x == 0) rn[b] = 1.f / fmaxf(sqrtf(sm[0]), 1e-12f);
}

// weight transpose-split: src [K][N] fp32 -> dst [N][ldk] hi/lo (single big job)
__global__ void k_wsplit(const float* __restrict__ src, int K, int N,
                         __half* __restrict__ dh, __half* __restrict__ dl, int ldk)
{
    __shared__ float t[32][33];
    int n0 = blockIdx.x * 32, k0 = blockIdx.y * 32;
#pragma unroll
    for (int j = 0; j < 4; j++) {
        int k = k0 + threadIdx.y + j * 8;
        int n = n0 + threadIdx.x;
        t[threadIdx.y + j * 8][threadIdx.x] =
            (k < K && n < N) ? src[(size_t)k * N + n] : 0.f;
    }
    __syncthreads();
#pragma unroll
    for (int j = 0; j < 4; j++) {
        int n = n0 + threadIdx.y + j * 8;
        int k = k0 + threadIdx.x;
        if (n < N && k < K) {
            float v = t[threadIdx.x][threadIdx.y + j * 8];
            __half h, l; hsplit(v, h, l);
            dh[(size_t)n * ldk + k] = h;
            dl[(size_t)n * ldk + k] = l;
        }
    }
}

// batched small weight splits: one launch for all small matrices
struct WJob { const float* src; __half* dh; __half* dl; int K, N, ldk, tilesX, tileBase; };
struct WJobs { WJob j[9]; };
__global__ void k_wsplit_all(WJobs jobs) {
    __shared__ float t[32][33];
    int b = blockIdx.x;
    int ji = 0;
#pragma unroll
    for (int q = 1; q < 9; q++)
        if (b >= jobs.j[q].tileBase) ji = q;
    const WJob jb = jobs.j[ji];
    int local = b - jb.tileBase;
    int n0 = (local % jb.tilesX) * 32;
    int k0 = (local / jb.tilesX) * 32;
#pragma unroll
    for (int j = 0; j < 4; j++) {
        int k = k0 + threadIdx.y + j * 8;
        int n = n0 + threadIdx.x;
        t[threadIdx.y + j * 8][threadIdx.x] =
            (k < jb.K && n < jb.N) ? jb.src[(size_t)k * jb.N + n] : 0.f;
    }
    __syncthreads();
#pragma unroll
    for (int j = 0; j < 4; j++) {
        int n = n0 + threadIdx.y + j * 8;
        int k = k0 + threadIdx.x;
        if (n < jb.N && k < jb.K) {
            float v = t[threadIdx.x][threadIdx.y + j * 8];
            __half h, l; hsplit(v, h, l);
            jb.dh[(size_t)n * jb.ldk + k] = h;
            jb.dl[(size_t)n * jb.ldk + k] = l;
        }
    }
}

// ---------------- CSR build ----------------
__global__ void k_hist(int* __restrict__ cnt, const int* __restrict__ d1,
                       const int* __restrict__ d2) {
    int e = blockIdx.x * blockDim.x + threadIdx.x;
    if (e >= E2) return;
    int d = (e < N_EDGES) ? d1[e] : (d2[e - N_EDGES] + N_NODES);
    atomicAdd(&cnt[d], 1);
}
__global__ void k_dinv(float* __restrict__ dinv, const int* __restrict__ cnt) {
    int i = blockIdx.x * blockDim.x + threadIdx.x;
    if (i < N_STACK) dinv[i] = rsqrtf((float)cnt[i] + 1.f);
}
__global__ void __launch_bounds__(1024) k_scan(const int* __restrict__ cnt,
                                               int* __restrict__ rowptr,
                                               int* __restrict__ cursor) {
    __shared__ int sm[1024];
    const int CH = N_STACK / 1024;
    int t = threadIdx.x;
    int base = t * CH;
    int s = 0;
#pragma unroll 4
    for (int j = 0; j < CH; j++) s += cnt[base + j];
    sm[t] = s;
    __syncthreads();
    for (int off = 1; off < 1024; off <<= 1) {
        int v = (t >= off) ? sm[t - off] : 0;
        __syncthreads();
        sm[t] += v;
        __syncthreads();
    }
    int run = (t > 0) ? sm[t - 1] : 0;
    for (int j = 0; j < CH; j++) {
        rowptr[base + j] = run;
        cursor[base + j] = run;
        run += cnt[base + j];
    }
    if (t == 1023) rowptr[N_STACK] = run;
}
__global__ void k_bucket(int* __restrict__ cursor, int* __restrict__ csrc,
                         const int* __restrict__ s1, const int* __restrict__ d1,
                         const int* __restrict__ s2, const int* __restrict__ d2) {
    int e = blockIdx.x * blockDim.x + threadIdx.x;
    if (e >= E2) return;
    int s, d;
    if (e < N_EDGES) { s = s1[e]; d = d1[e]; }
    else             { s = s2[e - N_EDGES] + N_NODES; d = d2[e - N_EDGES] + N_NODES; }
    int pos = atomicAdd(&cursor[d], 1);
    csrc[pos] = s;
}

// ---------------- gather: fp32 in -> fp16 hi/lo planes out ----------------
template <int VEC>
__global__ void k_gatherH(__half* __restrict__ oh, __half* __restrict__ ol, int ldo,
                          const float* __restrict__ X1, const float* __restrict__ X2,
                          int ldin, int fvec,
                          const int* __restrict__ rowptr, const int* __restrict__ csrc,
                          const float* __restrict__ dinv)
{
    long long i = (long long)blockIdx.x * blockDim.x + threadIdx.x;
    if (i >= (long long)N_STACK * fvec) return;
    int n = (int)(i / fvec);
    int f = (int)(i - (long long)n * fvec) * VEC;

    const float* Xn = (n < N_NODES) ? X1 + (size_t)n * ldin
                                    : X2 + (size_t)(n - N_NODES) * ldin;
    float dn = dinv[n];
    int b0 = rowptr[n], b1 = rowptr[n + 1];

    float r[VEC];
#pragma unroll
    for (int q = 0; q < VEC; q++) r[q] = Xn[f + q] * dn;
    for (int j = b0; j < b1; j++) {
        int s = csrc[j];
        const float* Xs = (s < N_NODES) ? X1 + (size_t)s * ldin
                                        : X2 + (size_t)(s - N_NODES) * ldin;
        float ds = dinv[s];
        if (VEC == 4) {
            float4 u = *reinterpret_cast<const float4*>(Xs + f);
            r[0] += u.x * ds; r[1] += u.y * ds; r[2] += u.z * ds; r[3] += u.w * ds;
        } else {
            float2 u = *reinterpret_cast<const float2*>(Xs + f);
            r[0] += u.x * ds; r[1] += u.y * ds;
        }
    }
    __half* ph = oh + (size_t)n * ldo + f;
    __half* pl = ol + (size_t)n * ldo + f;
#pragma unroll
    for (int q = 0; q < VEC; q += 2) {
        __half h, l; __half2 hh, ll;
        hsplit(r[q] * dn, h, l);     hh.x = h; ll.x = l;
        hsplit(r[q + 1] * dn, h, l); hh.y = h; ll.y = l;
        *(__half2*)(ph + q) = hh;
        *(__half2*)(pl + q) = ll;
    }
}

// ---------------- misc ----------------
__global__ void k_pool(__half* __restrict__ ph, __half* __restrict__ pl,
                       const float* __restrict__ X) {
    int i = blockIdx.x * blockDim.x + threadIdx.x;
    if (i >= 2 * BATCH * 312) return;
    int gg = i / 312, f = i - gg * 312;
    const float* p = X + (size_t)gg * NPG * 312 + f;
    float m = p[0];
#pragma unroll 8
    for (int j = 1; j < NPG; j++) m = fmaxf(m, p[(size_t)j * 312]);
    __half h, l; hsplit(m, h, l);
    ph[(size_t)gg * 320 + f] = h;
    pl[(size_t)gg * 320 + f] = l;
}

__global__ void k_cellepi(__half* __restrict__ oh, __half* __restrict__ ol,
                          const float* __restrict__ acc,
                          const float* __restrict__ rn, const float* __restrict__ bias)
{
    int i = blockIdx.x * blockDim.x + threadIdx.x;
    if (i >= BATCH * 512) return;
    int r = i >> 9, c = i & 511;
    float v = fmaxf(acc[i] * rn[r] + bias[c], 0.f);
    __half h, l; hsplit(v, h, l);
    oh[i] = h; ol[i] = l;
}

__global__ void k_xcpack(__half* __restrict__ xh, __half* __restrict__ xl,
                         const float* __restrict__ gt) {
    int i = blockIdx.x * blockDim.x + threadIdx.x;
    if (i >= BATCH * 256) return;
    int b = i >> 8, c = i & 255;
    float v = (c < 128) ? gt[(size_t)b * 128 + c]
                        : gt[(size_t)(BATCH + b) * 128 + (c - 128)];
    __half h, l; hsplit(v, h, l);
    xh[(size_t)b * 384 + c] = h;
    xl[(size_t)b * 384 + c] = l;
}

__global__ void k_out(const float* __restrict__ f2, const float* __restrict__ Wo,
                      const float* __restrict__ bo, float* __restrict__ out) {
    int i = blockIdx.x * blockDim.x + threadIdx.x;
    if (i >= BATCH * 2) return;
    int b = i >> 1, o = i & 1;
    float s = bo[o];
    const float* fp = f2 + (size_t)b * 128;
#pragma unroll 8
    for (int k = 0; k < 128; k++) s += fp[k] * Wo[k * 2 + o];
    out[i] = s;
}

// ---------------- host ----------------
static inline int cdiv(int a, int b) { return (a + b - 1) / b; }
#define SMEM_G3 (8 * 128 * PADK * (int)sizeof(__half))   // 81920 B
#define SMEM_G2 (6 * 128 * PADK * (int)sizeof(__half))   // 61440 B
#define SYM(p, s) cudaGetSymbolAddress((void**)&(p), s)

extern "C" void kernel_launch(void* const* d_in, const int* in_sizes, int n_in,
                              void* d_out, int out_size)
{
    const float* x1   = (const float*)d_in[0];
    const int*   ei1  = (const int*)  d_in[1];
    const float* x2   = (const float*)d_in[3];
    const int*   ei2  = (const int*)  d_in[4];
    const float* cell = (const float*)d_in[6];
    const float *Wc1 = (const float*)d_in[7],  *bc1 = (const float*)d_in[8];
    const float *Wc2 = (const float*)d_in[9],  *bc2 = (const float*)d_in[10];
    const float *Wc3 = (const float*)d_in[11], *bc3 = (const float*)d_in[12];
    const float *Wg1 = (const float*)d_in[13], *bg1 = (const float*)d_in[14];
    const float *Wg2 = (const float*)d_in[15], *bg2 = (const float*)d_in[16];
    const float *Wr1 = (const float*)d_in[17], *br1 = (const float*)d_in[18];
    const float *Wr2 = (const float*)d_in[19], *br2 = (const float*)d_in[20];
    const float *Wr3 = (const float*)d_in[21], *br3 = (const float*)d_in[22];
    const float *Wf1 = (const float*)d_in[23], *bf1 = (const float*)d_in[24];
    const float *Wf2 = (const float*)d_in[25], *bf2 = (const float*)d_in[26];
    const float *Wo  = (const float*)d_in[27], *bo  = (const float*)d_in[28];

    const int* s1 = ei1;  const int* d1 = ei1 + N_EDGES;
    const int* s2 = ei2;  const int* d2 = ei2 + N_EDGES;

    cudaFuncSetAttribute(gemm_hs<true>,  cudaFuncAttributeMaxDynamicSharedMemorySize, SMEM_G3);
    cudaFuncSetAttribute(gemm_hs<false>, cudaFuncAttributeMaxDynamicSharedMemorySize, SMEM_G2);

    float *H_, *B_, *acc_, *gt_, *f2_, *rn_, *dinv_;
    int *cnt_, *rowptr_, *cursor_, *csrc_;
    __half *cellh, *wr1th, *wr1tl;
    __half *A1h, *A1l, *A2h, *A2l, *A3h, *A3l;
    __half *wc1th, *wc1tl, *wc2th, *wc2tl, *wc3th, *wc3tl;
    __half *wg1th, *wg1tl, *wg2th, *wg2tl;
    __half *wr2th, *wr2tl, *wr3th, *wr3tl, *wf1th, *wf1tl, *wf2th, *wf2tl;
    __half *poolh, *pooll, *p1h, *p1l, *cv1h, *cv1l, *cv2h, *cv2l;
    __half *xch, *xcl, *f1h, *f1l;

    SYM(H_, g_H); SYM(B_, g_B2); SYM(acc_, g_acc); SYM(gt_, g_gt);
    SYM(f2_, g_f2); SYM(rn_, g_rn); SYM(dinv_, g_dinv);
    SYM(cnt_, g_cnt); SYM(rowptr_, g_rowptr); SYM(cursor_, g_cursor); SYM(csrc_, g_csrc);
    SYM(cellh, g_cellh); SYM(wr1th, g_wr1th); SYM(wr1tl, g_wr1tl);
    SYM(A1h, g_A1h); SYM(A1l, g_A1l); SYM(A2h, g_A2h); SYM(A2l, g_A2l);
    SYM(A3h, g_A3h); SYM(A3l, g_A3l);
    SYM(wc1th, g_wc1th); SYM(wc1tl, g_wc1tl); SYM(wc2th, g_wc2th); SYM(wc2tl, g_wc2tl);
    SYM(wc3th, g_wc3th); SYM(wc3tl, g_wc3tl);
    SYM(wg1th, g_wg1th); SYM(wg1tl, g_wg1tl); SYM(wg2th, g_wg2th); SYM(wg2tl, g_wg2tl);
    SYM(wr2th, g_wr2th); SYM(wr2tl, g_wr2tl); SYM(wr3th, g_wr3th); SYM(wr3tl, g_wr3tl);
    SYM(wf1th, g_wf1th); SYM(wf1tl, g_wf1tl); SYM(wf2th, g_wf2th); SYM(wf2tl, g_wf2tl);
    SYM(poolh, g_poolh); SYM(pooll, g_pooll); SYM(p1h, g_p1h); SYM(p1l, g_p1l);
    SYM(cv1h, g_cv1h); SYM(cv1l, g_cv1l); SYM(cv2h, g_cv2h); SYM(cv2l, g_cv2l);
    SYM(xch, g_xch); SYM(xcl, g_xcl); SYM(f1h, g_f1h); SYM(f1l, g_f1l);

    dim3 blk32(32, 8);

    // ---- prep: cell (hi-only) + Wr1 (big) + all small weights in ONE launch ----
    k_cellprep<<<BATCH, 256>>>(cell, cellh, rn_);
    k_wsplit<<<dim3(16, 1165), blk32>>>(Wr1, 37261, 512, wr1th, wr1tl, KCELL);
    {
        WJobs jobs;
        int base = 0;
        auto add = [&](int idx, const float* src, __half* dh, __half* dl,
                       int K, int N, int ldk) {
            int tx = cdiv(N, 32), ty = cdiv(K, 32);
            jobs.j[idx] = {src, dh, dl, K, N, ldk, tx, base};
            base += tx * ty;
        };
        add(0, Wc1, wc1th, wc1tl, 78, 78, 96);
        add(1, Wc2, wc2th, wc2tl, 78, 156, 96);
        add(2, Wc3, wc3th, wc3tl, 156, 312, 160);
        add(3, Wg1, wg1th, wg1tl, 312, 156, 320);
        add(4, Wg2, wg2th, wg2tl, 156, 128, 160);
        add(5, Wr2, wr2th, wr2tl, 512, 256, 512);
        add(6, Wr3, wr3th, wr3tl, 256, 128, 256);
        add(7, Wf1, wf1th, wf1tl, 384, 512, 384);
        add(8, Wf2, wf2th, wf2tl, 512, 128, 512);
        k_wsplit_all<<<base, blk32>>>(jobs);
    }

    // ---- cell branch: 2-pass big GEMM (A hi-only), split-K ----
    cudaMemsetAsync(acc_, 0, (size_t)BATCH * 512 * sizeof(float));
    gemm_hs<false><<<dim3(4, 8, SPLITK), 256, SMEM_G2>>>(
        cellh, nullptr, KCELL, wr1th, wr1tl, KCELL,
        acc_, 512, nullptr, nullptr, 0,
        BATCH, 512, KCELL, KCELL / SPLITK, nullptr, 0, 1);
    k_cellepi<<<cdiv(BATCH * 512, 256), 256>>>(cv1h, cv1l, acc_, rn_, br1);
    gemm_hs<true><<<dim3(2, 8, 1), 256, SMEM_G3>>>(
        cv1h, cv1l, 512, wr2th, wr2tl, 512,
        nullptr, 0, cv2h, cv2l, 256,
        BATCH, 256, 512, 512, br2, 1, 0);
    gemm_hs<true><<<dim3(1, 8, 1), 256, SMEM_G3>>>(
        cv2h, cv2l, 256, wr3th, wr3tl, 256,
        nullptr, 0, xch + 256, xcl + 256, 384,
        BATCH, 128, 256, 256, br3, 0, 0);

    // ---- CSR build ----
    cudaMemsetAsync(cnt_, 0, N_STACK * sizeof(int));
    k_hist  <<<cdiv(E2, 256), 256>>>(cnt_, d1, d2);
    k_dinv  <<<cdiv(N_STACK, 256), 256>>>(dinv_, cnt_);
    k_scan  <<<1, 1024>>>(cnt_, rowptr_, cursor_);
    k_bucket<<<cdiv(E2, 256), 256>>>(cursor_, csrc_, s1, d1, s2, d2);

    // ---- conv1 ----
    k_gatherH<2><<<cdiv(N_STACK * 39, 256), 256>>>(A1h, A1l, 96, x1, x2, 78, 39,
                                                   rowptr_, csrc_, dinv_);
    gemm_hs<true><<<dim3(1, 640, 1), 256, SMEM_G3>>>(
        A1h, A1l, 96, wc1th, wc1tl, 96,
        H_, 78, nullptr, nullptr, 0,
        N_STACK, 78, 96, 96, bc1, 1, 0);

    // ---- conv2 ----
    k_gatherH<2><<<cdiv(N_STACK * 39, 256), 256>>>(A2h, A2l, 96, H_,
                                                   H_ + (size_t)N_NODES * 78, 78, 39,
                                                   rowptr_, csrc_, dinv_);
    gemm_hs<true><<<dim3(2, 640, 1), 256, SMEM_G3>>>(
        A2h, A2l, 96, wc2th, wc2tl, 96,
        B_, 156, nullptr, nullptr, 0,
        N_STACK, 156, 96, 96, bc2, 1, 0);

    // ---- conv3 ----
    k_gatherH<4><<<cdiv(N_STACK * 39, 256), 256>>>(A3h, A3l, 160, B_,
                                                   B_ + (size_t)N_NODES * 156, 156, 39,
                                                   rowptr_, csrc_, dinv_);
    gemm_hs<true><<<dim3(3, 640, 1), 256, SMEM_G3>>>(
        A3h, A3l, 160, wc3th, wc3tl, 160,
        H_, 312, nullptr, nullptr, 0,
        N_STACK, 312, 160, 160, bc3, 1, 0);

    // ---- pool + shared drug head (M = 2048) ----
    k_pool<<<cdiv(2 * BATCH * 312, 256), 256>>>(poolh, pooll, H_);
    gemm_hs<true><<<dim3(2, 16, 1), 256, SMEM_G3>>>(
        poolh, pooll, 320, wg1th, wg1tl, 320,
        nullptr, 0, p1h, p1l, 160,
        2 * BATCH, 156, 320, 320, bg1, 1, 0);
    gemm_hs<true><<<dim3(1, 16, 1), 256, SMEM_G3>>>(
        p1h, p1l, 160, wg2th, wg2tl, 160,
        gt_, 128, nullptr, nullptr, 0,
        2 * BATCH, 128, 160, 160, bg2, 0, 0);
    k_xcpack<<<cdiv(BATCH * 256, 256), 256>>>(xch, xcl, gt_);

    // ---- fusion head ----
    gemm_hs<true><<<dim3(4, 8, 1), 256, SMEM_G3>>>(
        xch, xcl, 384, wf1th, wf1tl, 384,
        nullptr, 0, f1h, f1l, 512,
        BATCH, 512, 384, 384, bf1, 1, 0);
    gemm_hs<true><<<dim3(1, 8, 1), 256, SMEM_G3>>>(
        f1h, f1l, 512, wf2th, wf2tl, 512,
        f2_, 128, nullptr, nullptr, 0,
        BATCH, 128, 512, 512, bf2, 1, 0);
    k_out<<<cdiv(BATCH * 2, 256), 256>>>(f2_, Wo, bo, (float*)d_out);
}

// round 7
// speedup vs baseline: 7.6399x; 1.0658x over previous
#include <cuda_runtime.h>
#include <cuda_fp16.h>
#include <cstdint>
#include <cstddef>

#define N_NODES 40960
#define N_STACK 81920
#define N_EDGES 131072
#define E2      262144
#define BATCH   1024
#define NPG     40
#define PADK    40
#define KCELL   37376      // 37261 padded to x32
#define KRAW    37261
#define SPLITK  8

// ---------------- fp32 scratch ----------------
__device__ float g_H  [N_STACK * 312];
__device__ float g_B2 [N_STACK * 156];
__device__ float g_acc[BATCH * 512];
__device__ float g_gt [2 * BATCH * 128];
__device__ float g_f2 [BATCH * 128];
__device__ float g_rn [BATCH];
__device__ float g_dinv[N_STACK];
__device__ int   g_cnt[N_STACK];
__device__ int   g_rowptr[N_STACK + 1];
__device__ int   g_cursor[N_STACK];
__device__ int   g_csrc[E2];

// ---------------- fp16 planes (pads never written -> stay 0) ----------------
__device__ __align__(16) __half g_cellh[BATCH * KCELL];

__device__ __align__(16) __half g_A1h[N_STACK * 96],  g_A1l[N_STACK * 96];
__device__ __align__(16) __half g_A2h[N_STACK * 96],  g_A2l[N_STACK * 96];
__device__ __align__(16) __half g_A3h[N_STACK * 160], g_A3l[N_STACK * 160];

// weights: k-major [Kpad][ldn], pure split (no transpose)
__device__ __align__(16) __half g_wc1h[96 * 128],  g_wc1l[96 * 128];
__device__ __align__(16) __half g_wc2h[96 * 256],  g_wc2l[96 * 256];
__device__ __align__(16) __half g_wc3h[160 * 384], g_wc3l[160 * 384];
__device__ __align__(16) __half g_wg1h[320 * 256], g_wg1l[320 * 256];
__device__ __align__(16) __half g_wg2h[160 * 128], g_wg2l[160 * 128];
__device__ __align__(16) __half g_wr2h[512 * 256], g_wr2l[512 * 256];
__device__ __align__(16) __half g_wr3h[256 * 128], g_wr3l[256 * 128];
__device__ __align__(16) __half g_wf1h[384 * 512], g_wf1l[384 * 512];
__device__ __align__(16) __half g_wf2h[512 * 128], g_wf2l[512 * 128];

__device__ __align__(16) __half g_poolh[2 * BATCH * 320], g_pooll[2 * BATCH * 320];
__device__ __align__(16) __half g_p1h [2 * BATCH * 160],  g_p1l [2 * BATCH * 160];
__device__ __align__(16) __half g_cv1h[BATCH * 512], g_cv1l[BATCH * 512];
__device__ __align__(16) __half g_cv2h[BATCH * 256], g_cv2l[BATCH * 256];
__device__ __align__(16) __half g_xch [BATCH * 384], g_xcl [BATCH * 384];
__device__ __align__(16) __half g_f1h [BATCH * 512], g_f1l [BATCH * 512];

// ---------------- helpers ----------------
__device__ __forceinline__ void cp16(void* dst, const void* src) {
    unsigned d = (unsigned)__cvta_generic_to_shared(dst);
    asm volatile("cp.async.cg.shared.global [%0], [%1], 16;\n" :: "r"(d), "l"(src));
}
__device__ __forceinline__ void hsplit(float v, __half& h, __half& l) {
    h = __float2half_rn(v);
    l = __float2half_rn(v - __half2float(h));
}
__device__ __forceinline__ void ldsm4(unsigned& r0, unsigned& r1, unsigned& r2,
                                      unsigned& r3, unsigned a) {
    asm volatile("ldmatrix.sync.aligned.m8n8.x4.shared.b16 {%0,%1,%2,%3}, [%4];"
                 : "=r"(r0), "=r"(r1), "=r"(r2), "=r"(r3) : "r"(a));
}
__device__ __forceinline__ void ldsm4t(unsigned& r0, unsigned& r1, unsigned& r2,
                                       unsigned& r3, unsigned a) {
    asm volatile("ldmatrix.sync.aligned.m8n8.x4.trans.shared.b16 {%0,%1,%2,%3}, [%4];"
                 : "=r"(r0), "=r"(r1), "=r"(r2), "=r"(r3) : "r"(a));
}

#define MMA16(d, a, b)                                                           \
    asm volatile(                                                                \
        "mma.sync.aligned.m16n8k16.row.col.f32.f16.f16.f32 "                     \
        "{%0,%1,%2,%3},{%4,%5,%6,%7},{%8,%9},{%0,%1,%2,%3};"                     \
        : "+f"((d)[0]), "+f"((d)[1]), "+f"((d)[2]), "+f"((d)[3])                 \
        : "r"((a)[0]), "r"((a)[1]), "r"((a)[2]), "r"((a)[3]),                    \
          "r"((b)[0]), "r"((b)[1]))

// ---------------- GEMM v2: ldmatrix + swizzled k-major B ----------------
// Tile 128x128x32, 8 warps (2m x 4n), warp 64x32.
// MODE 0: B pre-split fp16 [K][ldb], 3-pass (ah*bh+ah*bl+al*bh).
// MODE 1: B fp32 [K][ldb] direct (cell GEMM), split at staging, A hi-only 2-pass.
template<int MODE>
__global__ void __launch_bounds__(256, 2) gemm_v2(
    const __half* __restrict__ Ah, const __half* __restrict__ Al, int lda,
    const __half* __restrict__ Bh, const __half* __restrict__ Bl,
    const float*  __restrict__ Bf, int ldb, int kLimit,
    float* C, int ldc, __half* Ch, __half* Cl, int ldch,
    int M, int N, int kTot, int kChunk,
    const float* __restrict__ bias, int relu, int atomic)
{
    extern __shared__ __align__(16) __half smem[];
    const int ASZ = 128 * PADK;            // halves per A stage
    const int BSZ = 32 * 128;              // halves per B stage (one plane)
    const int nAplanes = (MODE == 0) ? 2 : 1;
    __half* AsH = smem;                                    // [2][ASZ]
    __half* AsL = smem + 2 * ASZ;                          // MODE0 only
    __half* BsH = smem + 2 * nAplanes * ASZ;               // [2][BSZ]
    __half* BsL = BsH + 2 * BSZ;

    const int tid  = threadIdx.x;
    const int lane = tid & 31;
    const int wid  = tid >> 5;
    const int wm   = wid >> 2;
    const int wn   = wid & 3;
    const int rowBase = blockIdx.y * 128;
    const int colBase = blockIdx.x * 128;
    const int kStart  = blockIdx.z * kChunk;
    const int kEnd    = min(kTot, kStart + kChunk);
    const int T       = (kEnd - kStart) >> 5;

    // lane-constant fragment address components
    const int qr  = lane & 7;
    const int grp = lane >> 3;
    const int aRowOff = qr + ((grp & 1) << 3);
    const int aColOff = (grp & 2) << 2;
    const int bKOff   = qr + ((grp & 1) << 3);
    const int bNOff   = (grp & 2) << 2;

    const unsigned sBase = (unsigned)__cvta_generic_to_shared(smem);
    const unsigned aHiB  = sBase;
    const unsigned aLoB  = sBase + 2 * ASZ * 2;
    const unsigned bHiB  = sBase + 2 * nAplanes * ASZ * 2;
    const unsigned bLoB  = bHiB + 2 * BSZ * 2;

    float acc[4][4][4] = {};

    // ---- A staging via cp.async ----
    auto stageA = [&](int s, int k0) {
#pragma unroll
        for (int i = 0; i < 2; i++) {
            int c = tid + i * 256;
            int r = c >> 2, cc = (c & 3) * 8;
            size_t ga = (size_t)(rowBase + r) * lda + k0 + cc;
            int so = r * PADK + cc;
            cp16(AsH + s * ASZ + so, Ah + ga);
            if (MODE == 0) cp16(AsL + s * ASZ + so, Al + ga);
        }
    };
    // ---- B staging ----
    auto stageB16 = [&](int s, int k0) {    // MODE 0: cp.async both planes, swizzled
#pragma unroll
        for (int i = 0; i < 2; i++) {
            int c = tid + i * 256;
            int k = c >> 4, ci = c & 15;
            int sw = ci ^ (k & 7);
            int so = k * 128 + sw * 8;
            size_t gb = (size_t)(k0 + k) * ldb + colBase + ci * 8;
            cp16(BsH + s * BSZ + so, Bh + gb);
            cp16(BsL + s * BSZ + so, Bl + gb);
        }
    };
    float4 rb[4];                           // MODE 1 register prefetch
    const int bK = tid >> 3;                // 0..31
    auto loadBf = [&](int k0) {
        int row = k0 + bK;
        const float* p = Bf + (size_t)row * ldb + colBase + (tid & 7) * 16;
        bool ok = row < kLimit;
#pragma unroll
        for (int j = 0; j < 4; j++)
            rb[j] = ok ? *(const float4*)(p + j * 4)
                       : make_float4(0.f, 0.f, 0.f, 0.f);
    };
    auto stsB = [&](int s) {
#pragma unroll
        for (int j = 0; j < 4; j++) {
            int n = (tid & 7) * 16 + j * 4;
            int off = bK * 128 + (((n >> 3) ^ (bK & 7)) << 3) + (n & 7);
            __half h0, l0, h1, l1, h2, l2, h3, l3;
            hsplit(rb[j].x, h0, l0); hsplit(rb[j].y, h1, l1);
            hsplit(rb[j].z, h2, l2); hsplit(rb[j].w, h3, l3);
            __half2 ph0 = __halves2half2(h0, h1), ph1 = __halves2half2(h2, h3);
            __half2 pl0 = __halves2half2(l0, l1), pl1 = __halves2half2(l2, l3);
            uint2 uh = { *(unsigned*)&ph0, *(unsigned*)&ph1 };
            uint2 ul = { *(unsigned*)&pl0, *(unsigned*)&pl1 };
            *(uint2*)(BsH + s * BSZ + off) = uh;
            *(uint2*)(BsL + s * BSZ + off) = ul;
        }
    };

    if (MODE == 1) loadBf(kStart);
    stageA(0, kStart);
    if (MODE == 0) stageB16(0, kStart);
    asm volatile("cp.async.commit_group;\n");

    for (int t = 0; t < T; t++) {
        const int s = t & 1;
        asm volatile("cp.async.wait_group 0;\n");
        if (MODE == 1) stsB(s);
        __syncthreads();
        if (t + 1 < T) {
            stageA(s ^ 1, kStart + ((t + 1) << 5));
            if (MODE == 0) stageB16(s ^ 1, kStart + ((t + 1) << 5));
            asm volatile("cp.async.commit_group;\n");
            if (MODE == 1) loadBf(kStart + ((t + 1) << 5));
        } else {
            asm volatile("cp.async.commit_group;\n");   // keep wait_group balanced
        }

        const unsigned aH = aHiB + s * ASZ * 2;
        const unsigned aL = aLoB + s * ASZ * 2;
        const unsigned bH = bHiB + s * BSZ * 2;
        const unsigned bL = bLoB + s * BSZ * 2;

#pragma unroll
        for (int ks = 0; ks < 2; ks++) {
            const int kb = ks * 16;
            unsigned bh[4][2], bl[4][2];
#pragma unroll
            for (int np = 0; np < 2; np++) {
                int n0 = wn * 32 + np * 16 + bNOff;
                int k  = kb + bKOff;
                unsigned off = (unsigned)(k * 128 + (((n0 >> 3) ^ qr) << 3)) * 2;
                unsigned r0, r1, r2, r3;
                ldsm4t(r0, r1, r2, r3, bH + off);
                bh[np * 2][0] = r0; bh[np * 2][1] = r1;
                bh[np * 2 + 1][0] = r2; bh[np * 2 + 1][1] = r3;
                ldsm4t(r0, r1, r2, r3, bL + off);
                bl[np * 2][0] = r0; bl[np * 2][1] = r1;
                bl[np * 2 + 1][0] = r2; bl[np * 2 + 1][1] = r3;
            }
#pragma unroll
            for (int mt = 0; mt < 4; mt++) {
                int row = wm * 64 + mt * 16 + aRowOff;
                unsigned off = (unsigned)(row * PADK + kb + aColOff) * 2;
                unsigned ah[4], al[4];
                ldsm4(ah[0], ah[1], ah[2], ah[3], aH + off);
                if (MODE == 0) ldsm4(al[0], al[1], al[2], al[3], aL + off);
#pragma unroll
                for (int nt = 0; nt < 4; nt++) {
                    MMA16(acc[mt][nt], ah, bh[nt]);
                    MMA16(acc[mt][nt], ah, bl[nt]);
                    if (MODE == 0) MMA16(acc[mt][nt], al, bh[nt]);
                }
            }
        }
        __syncthreads();
    }

    const int g   = lane >> 2;
    const int tg2 = (lane & 3) * 2;
#pragma unroll
    for (int mt = 0; mt < 4; mt++)
#pragma unroll
        for (int nt = 0; nt < 4; nt++) {
            int r0 = rowBase + wm * 64 + mt * 16 + g;
            int cb = colBase + wn * 32 + nt * 8 + tg2;
            if (cb >= N) continue;
            float* a = acc[mt][nt];
            if (atomic) {
                atomicAdd(&C[(size_t)r0 * ldc + cb],           a[0]);
                atomicAdd(&C[(size_t)r0 * ldc + cb + 1],       a[1]);
                atomicAdd(&C[(size_t)(r0 + 8) * ldc + cb],     a[2]);
                atomicAdd(&C[(size_t)(r0 + 8) * ldc + cb + 1], a[3]);
            } else {
                float b0 = bias ? bias[cb] : 0.f;
                float b1 = bias ? bias[cb + 1] : 0.f;
                float v0 = a[0] + b0, v1 = a[1] + b1, v2 = a[2] + b0, v3 = a[3] + b1;
                if (relu) {
                    v0 = fmaxf(v0, 0.f); v1 = fmaxf(v1, 0.f);
                    v2 = fmaxf(v2, 0.f); v3 = fmaxf(v3, 0.f);
                }
                if (C) {
                    C[(size_t)r0 * ldc + cb] = v0;
                    C[(size_t)r0 * ldc + cb + 1] = v1;
                    C[(size_t)(r0 + 8) * ldc + cb] = v2;
                    C[(size_t)(r0 + 8) * ldc + cb + 1] = v3;
                }
                if (Ch) {
                    __half h, l; __half2 hh, ll;
                    hsplit(v0, h, l); hh.x = h; ll.x = l;
                    hsplit(v1, h, l); hh.y = h; ll.y = l;
                    *(__half2*)(Ch + (size_t)r0 * ldch + cb) = hh;
                    *(__half2*)(Cl + (size_t)r0 * ldch + cb) = ll;
                    hsplit(v2, h, l); hh.x = h; ll.x = l;
                    hsplit(v3, h, l); hh.y = h; ll.y = l;
                    *(__half2*)(Ch + (size_t)(r0 + 8) * ldch + cb) = hh;
                    *(__half2*)(Cl + (size_t)(r0 + 8) * ldch + cb) = ll;
                }
            }
        }
}

// ---------------- prep kernels ----------------
__global__ void k_cellprep(const float* __restrict__ cell,
                           __half* __restrict__ ch, float* __restrict__ rn)
{
    __shared__ float sm[256];
    int b = blockIdx.x;
    const float* row = cell + (size_t)b * KRAW;
    __half* oh = ch + (size_t)b * KCELL;
    float s = 0.f;
    for (int i = threadIdx.x; i < KRAW; i += 256) {
        float v = row[i];
        s += v * v;
        oh[i] = __float2half_rn(v);
    }
    sm[threadIdx.x] = s;
    __syncthreads();
    for (int off = 128; off > 0; off >>= 1) {
        if (threadIdx.x < off) sm[threadIdx.x] += sm[threadIdx.x + off];
        __syncthreads();
    }
    if (threadIdx.x == 0) rn[b] = 1.f / fmaxf(sqrtf(sm[0]), 1e-12f);
}

// batched pure splits (no transpose): src [K][N] fp32 -> [K][ldn] hi/lo
struct WJob { const float* src; __half* dh; __half* dl; int K, N, ldn; long long base; };
struct WJobs { WJob j[9]; long long total; };
__global__ void k_wsplit_all(WJobs jobs) {
    long long idx = (long long)blockIdx.x * blockDim.x + threadIdx.x;
    if (idx >= jobs.total) return;
    int ji = 0;
#pragma unroll
    for (int q = 1; q < 9; q++)
        if (idx >= jobs.j[q].base) ji = q;
    const WJob jb = jobs.j[ji];
    long long e = idx - jb.base;
    int k = (int)(e / jb.N);
    int n = (int)(e - (long long)k * jb.N);
    float v = jb.src[(size_t)k * jb.N + n];
    __half h, l; hsplit(v, h, l);
    jb.dh[(size_t)k * jb.ldn + n] = h;
    jb.dl[(size_t)k * jb.ldn + n] = l;
}

// ---------------- CSR build ----------------
__global__ void k_hist(int* __restrict__ cnt, const int* __restrict__ d1,
                       const int* __restrict__ d2) {
    int e = blockIdx.x * blockDim.x + threadIdx.x;
    if (e >= E2) return;
    int d = (e < N_EDGES) ? d1[e] : (d2[e - N_EDGES] + N_NODES);
    atomicAdd(&cnt[d], 1);
}
__global__ void k_dinv(float* __restrict__ dinv, const int* __restrict__ cnt) {
    int i = blockIdx.x * blockDim.x + threadIdx.x;
    if (i < N_STACK) dinv[i] = rsqrtf((float)cnt[i] + 1.f);
}
__global__ void __launch_bounds__(1024) k_scan(const int* __restrict__ cnt,
                                               int* __restrict__ rowptr,
                                               int* __restrict__ cursor) {
    __shared__ int sm[1024];
    const int CH = N_STACK / 1024;
    int t = threadIdx.x;
    int base = t * CH;
    int s = 0;
#pragma unroll 4
    for (int j = 0; j < CH; j++) s += cnt[base + j];
    sm[t] = s;
    __syncthreads();
    for (int off = 1; off < 1024; off <<= 1) {
        int v = (t >= off) ? sm[t - off] : 0;
        __syncthreads();
        sm[t] += v;
        __syncthreads();
    }
    int run = (t > 0) ? sm[t - 1] : 0;
    for (int j = 0; j < CH; j++) {
        rowptr[base + j] = run;
        cursor[base + j] = run;
        run += cnt[base + j];
    }
    if (t == 1023) rowptr[N_STACK] = run;
}
__global__ void k_bucket(int* __restrict__ cursor, int* __restrict__ csrc,
                         const int* __restrict__ s1, const int* __restrict__ d1,
                         const int* __restrict__ s2, const int* __restrict__ d2) {
    int e = blockIdx.x * blockDim.x + threadIdx.x;
    if (e >= E2) return;
    int s, d;
    if (e < N_EDGES) { s = s1[e]; d = d1[e]; }
    else             { s = s2[e - N_EDGES] + N_NODES; d = d2[e - N_EDGES] + N_NODES; }
    int pos = atomicAdd(&cursor[d], 1);
    csrc[pos] = s;
}

// ---------------- gather: fp32 in -> fp16 hi/lo planes out ----------------
template <int VEC>
__global__ void k_gatherH(__half* __restrict__ oh, __half* __restrict__ ol, int ldo,
                          const float* __restrict__ X1, const float* __restrict__ X2,
                          int ldin, int fvec,
                          const int* __restrict__ rowptr, const int* __restrict__ csrc,
                          const float* __restrict__ dinv)
{
    long long i = (long long)blockIdx.x * blockDim.x + threadIdx.x;
    if (i >= (long long)N_STACK * fvec) return;
    int n = (int)(i / fvec);
    int f = (int)(i - (long long)n * fvec) * VEC;

    const float* Xn = (n < N_NODES) ? X1 + (size_t)n * ldin
                                    : X2 + (size_t)(n - N_NODES) * ldin;
    float dn = dinv[n];
    int b0 = rowptr[n], b1 = rowptr[n + 1];

    float r[VEC];
#pragma unroll
    for (int q = 0; q < VEC; q++) r[q] = Xn[f + q] * dn;
    for (int j = b0; j < b1; j++) {
        int s = csrc[j];
        const float* Xs = (s < N_NODES) ? X1 + (size_t)s * ldin
                                        : X2 + (size_t)(s - N_NODES) * ldin;
        float ds = dinv[s];
        if (VEC == 4) {
            float4 u = *reinterpret_cast<const float4*>(Xs + f);
            r[0] += u.x * ds; r[1] += u.y * ds; r[2] += u.z * ds; r[3] += u.w * ds;
        } else {
            float2 u = *reinterpret_cast<const float2*>(Xs + f);
            r[0] += u.x * ds; r[1] += u.y * ds;
        }
    }
    __half* ph = oh + (size_t)n * ldo + f;
    __half* pl = ol + (size_t)n * ldo + f;
#pragma unroll
    for (int q = 0; q < VEC; q += 2) {
        __half h, l; __half2 hh, ll;
        hsplit(r[q] * dn, h, l);     hh.x = h; ll.x = l;
        hsplit(r[q + 1] * dn, h, l); hh.y = h; ll.y = l;
        *(__half2*)(ph + q) = hh;
        *(__half2*)(pl + q) = ll;
    }
}

// ---------------- misc ----------------
__global__ void k_pool(__half* __restrict__ ph, __half* __restrict__ pl,
                       const float* __restrict__ X) {
    int i = blockIdx.x * blockDim.x + threadIdx.x;
    if (i >= 2 * BATCH * 312) return;
    int gg = i / 312, f = i - gg * 312;
    const float* p = X + (size_t)gg * NPG * 312 + f;
    float m = p[0];
#pragma unroll 8
    for (int j = 1; j < NPG; j++) m = fmaxf(m, p[(size_t)j * 312]);
    __half h, l; hsplit(m, h, l);
    ph[(size_t)gg * 320 + f] = h;
    pl[(size_t)gg * 320 + f] = l;
}

__global__ void k_cellepi(__half* __restrict__ oh, __half* __restrict__ ol,
                          const float* __restrict__ acc,
                          const float* __restrict__ rn, const float* __restrict__ bias)
{
    int i = blockIdx.x * blockDim.x + threadIdx.x;
    if (i >= BATCH * 512) return;
    int r = i >> 9, c = i & 511;
    float v = fmaxf(acc[i] * rn[r] + bias[c], 0.f);
    __half h, l; hsplit(v, h, l);
    oh[i] = h; ol[i] = l;
}

__global__ void k_xcpack(__half* __restrict__ xh, __half* __restrict__ xl,
                         const float* __restrict__ gt) {
    int i = blockIdx.x * blockDim.x + threadIdx.x;
    if (i >= BATCH * 256) return;
    int b = i >> 8, c = i & 255;
    float v = (c < 128) ? gt[(size_t)b * 128 + c]
                        : gt[(size_t)(BATCH + b) * 128 + (c - 128)];
    __half h, l; hsplit(v, h, l);
    xh[(size_t)b * 384 + c] = h;
    xl[(size_t)b * 384 + c] = l;
}

__global__ void k_out(const float* __restrict__ f2, const float* __restrict__ Wo,
                      const float* __restrict__ bo, float* __restrict__ out) {
    int i = blockIdx.x * blockDim.x + threadIdx.x;
    if (i >= BATCH * 2) return;
    int b = i >> 1, o = i & 1;
    float s = bo[o];
    const float* fp = f2 + (size_t)b * 128;
#pragma unroll 8
    for (int k = 0; k < 128; k++) s += fp[k] * Wo[k * 2 + o];
    out[i] = s;
}

// ---------------- host ----------------
static inline int cdiv(int a, int b) { return (a + b - 1) / b; }
#define ASZ_H (128 * PADK)
#define BSZ_H (32 * 128)
#define SMEM_M0 ((4 * ASZ_H + 4 * BSZ_H) * (int)sizeof(__half))   // 73728
#define SMEM_M1 ((2 * ASZ_H + 4 * BSZ_H) * (int)sizeof(__half))   // 53248
#define SYM(p, s) cudaGetSymbolAddress((void**)&(p), s)

extern "C" void kernel_launch(void* const* d_in, const int* in_sizes, int n_in,
                              void* d_out, int out_size)
{
    const float* x1   = (const float*)d_in[0];
    const int*   ei1  = (const int*)  d_in[1];
    const float* x2   = (const float*)d_in[3];
    const int*   ei2  = (const int*)  d_in[4];
    const float* cell = (const float*)d_in[6];
    const float *Wc1 = (const float*)d_in[7],  *bc1 = (const float*)d_in[8];
    const float *Wc2 = (const float*)d_in[9],  *bc2 = (const float*)d_in[10];
    const float *Wc3 = (const float*)d_in[11], *bc3 = (const float*)d_in[12];
    const float *Wg1 = (const float*)d_in[13], *bg1 = (const float*)d_in[14];
    const float *Wg2 = (const float*)d_in[15], *bg2 = (const float*)d_in[16];
    const float *Wr1 = (const float*)d_in[17], *br1 = (const float*)d_in[18];
    const float *Wr2 = (const float*)d_in[19], *br2 = (const float*)d_in[20];
    const float *Wr3 = (const float*)d_in[21], *br3 = (const float*)d_in[22];
    const float *Wf1 = (const float*)d_in[23], *bf1 = (const float*)d_in[24];
    const float *Wf2 = (const float*)d_in[25], *bf2 = (const float*)d_in[26];
    const float *Wo  = (const float*)d_in[27], *bo  = (const float*)d_in[28];

    const int* s1 = ei1;  const int* d1 = ei1 + N_EDGES;
    const int* s2 = ei2;  const int* d2 = ei2 + N_EDGES;

    cudaFuncSetAttribute(gemm_v2<0>, cudaFuncAttributeMaxDynamicSharedMemorySize, SMEM_M0);
    cudaFuncSetAttribute(gemm_v2<1>, cudaFuncAttributeMaxDynamicSharedMemorySize, SMEM_M1);

    float *H_, *B_, *acc_, *gt_, *f2_, *rn_, *dinv_;
    int *cnt_, *rowptr_, *cursor_, *csrc_;
    __half *cellh;
    __half *A1h, *A1l, *A2h, *A2l, *A3h, *A3l;
    __half *wc1h, *wc1l, *wc2h, *wc2l, *wc3h, *wc3l;
    __half *wg1h, *wg1l, *wg2h, *wg2l;
    __half *wr2h, *wr2l, *wr3h, *wr3l, *wf1h, *wf1l, *wf2h, *wf2l;
    __half *poolh, *pooll, *p1h, *p1l, *cv1h, *cv1l, *cv2h, *cv2l;
    __half *xch, *xcl, *f1h, *f1l;

    SYM(H_, g_H); SYM(B_, g_B2); SYM(acc_, g_acc); SYM(gt_, g_gt);
    SYM(f2_, g_f2); SYM(rn_, g_rn); SYM(dinv_, g_dinv);
    SYM(cnt_, g_cnt); SYM(rowptr_, g_rowptr); SYM(cursor_, g_cursor); SYM(csrc_, g_csrc);
    SYM(cellh, g_cellh);
    SYM(A1h, g_A1h); SYM(A1l, g_A1l); SYM(A2h, g_A2h); SYM(A2l, g_A2l);
    SYM(A3h, g_A3h); SYM(A3l, g_A3l);
    SYM(wc1h, g_wc1h); SYM(wc1l, g_wc1l); SYM(wc2h, g_wc2h); SYM(wc2l, g_wc2l);
    SYM(wc3h, g_wc3h); SYM(wc3l, g_wc3l);
    SYM(wg1h, g_wg1h); SYM(wg1l, g_wg1l); SYM(wg2h, g_wg2h); SYM(wg2l, g_wg2l);
    SYM(wr2h, g_wr2h); SYM(wr2l, g_wr2l); SYM(wr3h, g_wr3h); SYM(wr3l, g_wr3l);
    SYM(wf1h, g_wf1h); SYM(wf1l, g_wf1l); SYM(wf2h, g_wf2h); SYM(wf2l, g_wf2l);
    SYM(poolh, g_poolh); SYM(pooll, g_pooll); SYM(p1h, g_p1h); SYM(p1l, g_p1l);
    SYM(cv1h, g_cv1h); SYM(cv1l, g_cv1l); SYM(cv2h, g_cv2h); SYM(cv2l, g_cv2l);
    SYM(xch, g_xch); SYM(xcl, g_xcl); SYM(f1h, g_f1h); SYM(f1l, g_f1l);

    // ---- prep: cell hi-split + all weight splits in ONE launch (no Wr1 prep!) ----
    k_cellprep<<<BATCH, 256>>>(cell, cellh, rn_);
    {
        WJobs jobs;
        long long base = 0;
        auto add = [&](int idx, const float* src, __half* dh, __half* dl,
                       int K, int N, int ldn) {
            jobs.j[idx] = {src, dh, dl, K, N, ldn, base};
            base += (long long)K * N;
        };
        add(0, Wc1, wc1h, wc1l, 78, 78, 128);
        add(1, Wc2, wc2h, wc2l, 78, 156, 256);
        add(2, Wc3, wc3h, wc3l, 156, 312, 384);
        add(3, Wg1, wg1h, wg1l, 312, 156, 256);
        add(4, Wg2, wg2h, wg2l, 156, 128, 128);
        add(5, Wr2, wr2h, wr2l, 512, 256, 256);
        add(6, Wr3, wr3h, wr3l, 256, 128, 128);
        add(7, Wf1, wf1h, wf1l, 384, 512, 512);
        add(8, Wf2, wf2h, wf2l, 512, 128, 128);
        jobs.total = base;
        k_wsplit_all<<<(int)cdiv((int)base, 256), 256>>>(jobs);
    }

    // ---- cell branch: fp32-B 2-pass split-K GEMM ----
    cudaMemsetAsync(acc_, 0, (size_t)BATCH * 512 * sizeof(float));
    gemm_v2<1><<<dim3(4, 8, SPLITK), 256, SMEM_M1>>>(
        cellh, nullptr, KCELL, nullptr, nullptr, Wr1, 512, KRAW,
        acc_, 512, nullptr, nullptr, 0,
        BATCH, 512, KCELL, KCELL / SPLITK, nullptr, 0, 1);
    k_cellepi<<<cdiv(BATCH * 512, 256), 256>>>(cv1h, cv1l, acc_, rn_, br1);
    gemm_v2<0><<<dim3(2, 8, 1), 256, SMEM_M0>>>(
        cv1h, cv1l, 512, wr2h, wr2l, nullptr, 256, 0,
        nullptr, 0, cv2h, cv2l, 256,
        BATCH, 256, 512, 512, br2, 1, 0);
    gemm_v2<0><<<dim3(1, 8, 1), 256, SMEM_M0>>>(
        cv2h, cv2l, 256, wr3h, wr3l, nullptr, 128, 0,
        nullptr, 0, xch + 256, xcl + 256, 384,
        BATCH, 128, 256, 256, br3, 0, 0);

    // ---- CSR build ----
    cudaMemsetAsync(cnt_, 0, N_STACK * sizeof(int));
    k_hist  <<<cdiv(E2, 256), 256>>>(cnt_, d1, d2);
    k_dinv  <<<cdiv(N_STACK, 256), 256>>>(dinv_, cnt_);
    k_scan  <<<1, 1024>>>(cnt_, rowptr_, cursor_);
    k_bucket<<<cdiv(E2, 256), 256>>>(cursor_, csrc_, s1, d1, s2, d2);

    // ---- conv1 ----
    k_gatherH<2><<<cdiv(N_STACK * 39, 256), 256>>>(A1h, A1l, 96, x1, x2, 78, 39,
                                                   rowptr_, csrc_, dinv_);
    gemm_v2<0><<<dim3(1, 640, 1), 256, SMEM_M0>>>(
        A1h, A1l, 96, wc1h, wc1l, nullptr, 128, 0,
        H_, 78, nullptr, nullptr, 0,
        N_STACK, 78, 96, 96, bc1, 1, 0);

    // ---- conv2 ----
    k_gatherH<2><<<cdiv(N_STACK * 39, 256), 256>>>(A2h, A2l, 96, H_,
                                                   H_ + (size_t)N_NODES * 78, 78, 39,
                                                   rowptr_, csrc_, dinv_);
    gemm_v2<0><<<dim3(2, 640, 1), 256, SMEM_M0>>>(
        A2h, A2l, 96, wc2h, wc2l, nullptr, 256, 0,
        B_, 156, nullptr, nullptr, 0,
        N_STACK, 156, 96, 96, bc2, 1, 0);

    // ---- conv3 ----
    k_gatherH<4><<<cdiv(N_STACK * 39, 256), 256>>>(A3h, A3l, 160, B_,
                                                   B_ + (size_t)N_NODES * 156, 156, 39,
                                                   rowptr_, csrc_, dinv_);
    gemm_v2<0><<<dim3(3, 640, 1), 256, SMEM_M0>>>(
        A3h, A3l, 160, wc3h, wc3l, nullptr, 384, 0,
        H_, 312, nullptr, nullptr, 0,
        N_STACK, 312, 160, 160, bc3, 1, 0);

    // ---- pool + shared drug head (M = 2048) ----
    k_pool<<<cdiv(2 * BATCH * 312, 256), 256>>>(poolh, pooll, H_);
    gemm_v2<0><<<dim3(2, 16, 1), 256, SMEM_M0>>>(
        poolh, pooll, 320, wg1h, wg1l, nullptr, 256, 0,
        nullptr, 0, p1h, p1l, 160,
        2 * BATCH, 156, 320, 320, bg1, 1, 0);
    gemm_v2<0><<<dim3(1, 16, 1), 256, SMEM_M0>>>(
        p1h, p1l, 160, wg2h, wg2l, nullptr, 128, 0,
        gt_, 128, nullptr, nullptr, 0,
        2 * BATCH, 128, 160, 160, bg2, 0, 0);
    k_xcpack<<<cdiv(BATCH * 256, 256), 256>>>(xch, xcl, gt_);

    // ---- fusion head ----
    gemm_v2<0><<<dim3(4, 8, 1), 256, SMEM_M0>>>(
        xch, xcl, 384, wf1h, wf1l, nullptr, 512, 0,
        nullptr, 0, f1h, f1l, 512,
        BATCH, 512, 384, 384, bf1, 1, 0);
    gemm_v2<0><<<dim3(1, 8, 1), 256, SMEM_M0>>>(
        f1h, f1l, 512, wf2h, wf2l, nullptr, 128, 0,
        f2_, 128, nullptr, nullptr, 0,
        BATCH, 128, 512, 512, bf2, 1, 0);
    k_out<<<cdiv(BATCH * 2, 256), 256>>>(f2_, Wo, bo, (float*)d_out);
}